// round 9
// baseline (speedup 1.0000x reference)
#include <cuda_runtime.h>
#include <cuda_bf16.h>
#include <cstdint>

// ---------------------------------------------------------------------------
// AttentionSampling: B=4, SQ=2048, SK=8192, D=H=512, F=4, fp32.
// GEMMs via mma.sync bf16 hi/lo 3-pass. Round 9: BM64xBN128 tile, 3-stage
// 24KB stages -> 3 CTAs/SM (6 warps/SMSP), 1 barrier/chunk, XOR swizzle.
// ---------------------------------------------------------------------------

#define DD 512
#define NQ  8192
#define NKV 32768
#define EPS 1e-5f

// fp32 scratch planes
#define F_Q   0
#define F_AO  (F_Q  + (size_t)NQ * DD)
#define F_O1  (F_AO + (size_t)NQ * DD)
#define F_FF  (F_O1 + (size_t)NQ * DD)
#define F_WP  (F_FF + (size_t)NQ * DD)          // w_part [NKV][16]
#define F_SW  (F_WP + (size_t)NKV * 16)         // sum-of-w [NQ]
#define F_TOT (F_SW + (size_t)NQ)
__device__ float g_scratch[F_TOT];

// bf16 hi/lo activation planes
#define B_QH  0
#define B_QL  (B_QH  + (size_t)NQ  * DD)
#define B_KH  (B_QL  + (size_t)NQ  * DD)
#define B_KL  (B_KH  + (size_t)NKV * DD)
#define B_VH  (B_KL  + (size_t)NKV * DD)        // downsampled value (NQ rows)
#define B_VL  (B_VH  + (size_t)NQ  * DD)
#define B_O1H (B_VL  + (size_t)NQ  * DD)
#define B_O1L (B_O1H + (size_t)NQ  * DD)
#define B_HH  (B_O1L + (size_t)NQ  * DD)
#define B_HL  (B_HH  + (size_t)NQ  * DD)
#define B_TOT (B_HL  + (size_t)NQ  * DD)
__device__ __nv_bfloat16 g_act[B_TOT];

// 5 weights x (hi,lo) x 512x512 bf16, stored [N][K] (transposed)
__device__ __nv_bfloat16 g_wsplit[5u * 2u * 512u * 512u];

// ---------------------------------------------------------------------------
// PTX helpers (base sm_100-legal)
// ---------------------------------------------------------------------------
__device__ __forceinline__ uint32_t smem_u32(const void* p) {
    uint32_t a;
    asm("{ .reg .u64 t; cvta.to.shared.u64 t, %1; cvt.u32.u64 %0, t; }"
        : "=r"(a) : "l"(p));
    return a;
}
__device__ __forceinline__ void ldsm_x4(uint32_t* r, uint32_t addr) {
    asm volatile("ldmatrix.sync.aligned.m8n8.x4.shared.b16 {%0,%1,%2,%3}, [%4];"
                 : "=r"(r[0]), "=r"(r[1]), "=r"(r[2]), "=r"(r[3]) : "r"(addr));
}
__device__ __forceinline__ void mma16816(float* c, const uint32_t* a, const uint32_t* b) {
    asm volatile(
        "mma.sync.aligned.m16n8k16.row.col.f32.bf16.bf16.f32 "
        "{%0,%1,%2,%3}, {%4,%5,%6,%7}, {%8,%9}, {%0,%1,%2,%3};"
        : "+f"(c[0]), "+f"(c[1]), "+f"(c[2]), "+f"(c[3])
        : "r"(a[0]), "r"(a[1]), "r"(a[2]), "r"(a[3]), "r"(b[0]), "r"(b[1]));
}
__device__ __forceinline__ void cp16(uint32_t saddr, const void* g) {
    asm volatile("cp.async.cg.shared.global [%0], [%1], 16;"
                 :: "r"(saddr), "l"(g) : "memory");
}
__device__ __forceinline__ void cp_commit() {
    asm volatile("cp.async.commit_group;" ::: "memory");
}
__device__ __forceinline__ void split_bf16(float x, __nv_bfloat16& h, __nv_bfloat16& l) {
    h = __float2bfloat16(x);
    l = __float2bfloat16(x - __bfloat162float(h));
}

// swizzled byte offset of 16B chunk (row, chunk) in a Nx64B plane
__device__ __forceinline__ uint32_t swz_off(uint32_t row, uint32_t chunk) {
    return row * 64u + ((chunk ^ ((row >> 1) & 3u)) << 4);
}

// ---------------------------------------------------------------------------
// Batched weight prep: W[k][n] fp32 -> Th[n][k], Tl[n][k] bf16 (5 weights)
// ---------------------------------------------------------------------------
__global__ void prep_weight5(
    const float* w0, const float* w1, const float* w2, const float* w3, const float* w4,
    __nv_bfloat16* base)
{
    const float* Ws[5] = {w0, w1, w2, w3, w4};
    const size_t WSZ = 512u * 512u;
    const float* W = Ws[blockIdx.z];
    __nv_bfloat16* Th = base + (size_t)blockIdx.z * 2u * WSZ;
    __nv_bfloat16* Tl = Th + WSZ;

    __shared__ float t[32][33];
    const int bx = blockIdx.x * 32, by = blockIdx.y * 32;
    const int tx = threadIdx.x, ty = threadIdx.y; // 32 x 8
#pragma unroll
    for (int i = 0; i < 32; i += 8)
        t[ty + i][tx] = W[(size_t)(by + ty + i) * DD + bx + tx];
    __syncthreads();
#pragma unroll
    for (int i = 0; i < 32; i += 8) {
        float x = t[tx][ty + i];
        __nv_bfloat16 h, l;
        split_bf16(x, h, l);
        size_t o = (size_t)(bx + ty + i) * DD + by + tx;
        Th[o] = h;
        Tl[o] = l;
    }
}

// ---------------------------------------------------------------------------
// fp32 -> bf16 hi/lo split (vectorized)
// ---------------------------------------------------------------------------
__global__ void __launch_bounds__(256) f32_to_hl(
    const float4* __restrict__ src, uint2* __restrict__ dh, uint2* __restrict__ dl)
{
    const int i = blockIdx.x * 256 + threadIdx.x;
    float4 x = src[i];
    __nv_bfloat16 hx, hy, hz, hw, lx, ly, lz, lw;
    split_bf16(x.x, hx, lx); split_bf16(x.y, hy, ly);
    split_bf16(x.z, hz, lz); split_bf16(x.w, hw, lw);
    __nv_bfloat162 h01, h23, l01, l23;
    h01.x = hx; h01.y = hy; h23.x = hz; h23.y = hw;
    l01.x = lx; l01.y = ly; l23.x = lz; l23.y = lw;
    uint2 hv, lv;
    hv.x = *(uint32_t*)&h01; hv.y = *(uint32_t*)&h23;
    lv.x = *(uint32_t*)&l01; lv.y = *(uint32_t*)&l23;
    dh[i] = hv;
    dl[i] = lv;
}

// ---------------------------------------------------------------------------
// HMMA GEMM: act(A[M,512] @ W[512,512] + bias)
// BM=64, BN=128, BK=32, 256 thr (8 warps 2m x 4n; warp tile 32x32).
// 3-stage cp.async pipeline (24KB stages), XOR swizzle, 1 barrier/chunk,
// launch_bounds(256,3) -> 3 CTAs/SM (6 warps/SMSP).
// DOTQ: k rows dotted with q rows instead of stored (w partials out).
// ---------------------------------------------------------------------------
#define BKC 32
#define NCH (DD / BKC)          // 16
#define PL_A 4096               // 64 rows x 64B
#define PL_B 8192               // 128 rows x 64B
#define SG_AH 0
#define SG_AL (PL_A)
#define SG_BH (2 * PL_A)
#define SG_BL (2 * PL_A + PL_B)
#define SG_SZ (2 * PL_A + 2 * PL_B)   // 24576
#define STAGES 3
#define GEMM_SMEM (STAGES * SG_SZ)    // 73728

template <bool RELU, bool OUT_HL, bool DOTQ, bool HASBIAS>
__global__ void __launch_bounds__(256, 3) gemm_hl(
    const __nv_bfloat16* __restrict__ Ah, const __nv_bfloat16* __restrict__ Al,
    const __nv_bfloat16* __restrict__ Bh, const __nv_bfloat16* __restrict__ Bl,
    const float* __restrict__ bias, float* __restrict__ C,
    __nv_bfloat16* __restrict__ Ch, __nv_bfloat16* __restrict__ Cl,
    const float* __restrict__ qdot, float* __restrict__ wpart)
{
    extern __shared__ char sm[];
    const uint32_t sb = smem_u32(sm);

    const int tid = threadIdx.x;
    const int lane = tid & 31, wid = tid >> 5;
    const int wm = (wid & 1) * 32;       // 2 m-warps
    const int wn = (wid >> 1) * 32;      // 4 n-warps
    const int bm = blockIdx.y * 64;
    const int bn = blockIdx.x * 128;

    float acc[2][4][4];
#pragma unroll
    for (int i = 0; i < 2; i++)
#pragma unroll
        for (int j = 0; j < 4; j++)
#pragma unroll
            for (int t = 0; t < 4; t++) acc[i][j][t] = 0.f;

    const uint32_t rowq = (uint32_t)(tid >> 2), segq = (uint32_t)(tid & 3);

    auto load_stage = [&](int c, int buf) {
        const uint32_t st = sb + buf * SG_SZ;
        const int kc = c * BKC;
        {   // A: 64 rows, 1 seg per thread
            uint32_t so = swz_off(rowq, segq);
            size_t ga = (size_t)(bm + rowq) * DD + kc + segq * 8;
            cp16(st + SG_AH + so, Ah + ga);
            cp16(st + SG_AL + so, Al + ga);
        }
        {   // B: 128 rows, 2 rows per thread
            uint32_t so0 = swz_off(rowq, segq);
            uint32_t so1 = swz_off(rowq + 64, segq);
            size_t gb0 = (size_t)(bn + rowq) * DD + kc + segq * 8;
            size_t gb1 = (size_t)(bn + rowq + 64) * DD + kc + segq * 8;
            cp16(st + SG_BH + so0, Bh + gb0);
            cp16(st + SG_BH + so1, Bh + gb1);
            cp16(st + SG_BL + so0, Bl + gb0);
            cp16(st + SG_BL + so1, Bl + gb1);
        }
        cp_commit();
    };

    const uint32_t a_r = (uint32_t)(wm + (lane & 15));
    const uint32_t a_ch = (uint32_t)(lane >> 4);        // chunk half (0/1)
    const uint32_t b_r = (uint32_t)(wn + ((lane >> 4) << 3) + (lane & 7));
    const uint32_t b_ch = (uint32_t)((lane >> 3) & 1);

    auto compute = [&](int buf) {
        const uint32_t st = sb + buf * SG_SZ;
#pragma unroll
        for (int ks = 0; ks < 2; ks++) {
            uint32_t ah[2][4], al[2][4], bh[2][4], bl[2][4];
            const uint32_t kch = (uint32_t)(ks * 2);
#pragma unroll
            for (int i = 0; i < 2; i++) {
                uint32_t off = swz_off(a_r + i * 16, kch + a_ch);
                ldsm_x4(ah[i], st + SG_AH + off);
                ldsm_x4(al[i], st + SG_AL + off);
            }
#pragma unroll
            for (int jp = 0; jp < 2; jp++) {
                uint32_t off = swz_off(b_r + jp * 16, kch + b_ch);
                ldsm_x4(bh[jp], st + SG_BH + off);
                ldsm_x4(bl[jp], st + SG_BL + off);
            }
#pragma unroll
            for (int i = 0; i < 2; i++)
#pragma unroll
                for (int j = 0; j < 4; j++)
                    mma16816(acc[i][j], ah[i], &bh[j >> 1][(j & 1) * 2]);
#pragma unroll
            for (int i = 0; i < 2; i++)
#pragma unroll
                for (int j = 0; j < 4; j++)
                    mma16816(acc[i][j], ah[i], &bl[j >> 1][(j & 1) * 2]);
#pragma unroll
            for (int i = 0; i < 2; i++)
#pragma unroll
                for (int j = 0; j < 4; j++)
                    mma16816(acc[i][j], al[i], &bh[j >> 1][(j & 1) * 2]);
        }
    };

    // 3-stage pipeline, one barrier per chunk.
    load_stage(0, 0);
    load_stage(1, 1);

#pragma unroll 1
    for (int c = 0; c < NCH; c++) {
        if (c < NCH - 1)
            asm volatile("cp.async.wait_group 1;" ::: "memory");
        else
            asm volatile("cp.async.wait_group 0;" ::: "memory");
        __syncthreads();
        if (c + 2 < NCH) load_stage(c + 2, (c + 2) % 3);
        compute(c % 3);
    }

    // ---------------- epilogue ----------------
    const int crow = lane >> 2, ccol = (lane & 3) * 2;

    if (DOTQ) {
        float dotr[2][2];
#pragma unroll
        for (int i = 0; i < 2; i++) { dotr[i][0] = 0.f; dotr[i][1] = 0.f; }
#pragma unroll
        for (int i = 0; i < 2; i++) {
            const int r0 = bm + wm + i * 16 + crow;
            const float* q0p = qdot + (size_t)(r0 >> 2) * DD;
            const float* q1p = qdot + (size_t)((r0 + 8) >> 2) * DD;
#pragma unroll
            for (int j = 0; j < 4; j++) {
                const int col = bn + wn + j * 8 + ccol;
                float bx = 0.f, by = 0.f;
                if (HASBIAS) {
                    float2 bv = *(const float2*)(bias + col);
                    bx = bv.x; by = bv.y;
                }
                float k00 = fmaxf(acc[i][j][0] + bx, 0.f);
                float k01 = fmaxf(acc[i][j][1] + by, 0.f);
                float k10 = fmaxf(acc[i][j][2] + bx, 0.f);
                float k11 = fmaxf(acc[i][j][3] + by, 0.f);
                float2 q0 = *(const float2*)(q0p + col);
                float2 q1 = *(const float2*)(q1p + col);
                dotr[i][0] += k00 * q0.x + k01 * q0.y;
                dotr[i][1] += k10 * q1.x + k11 * q1.y;
            }
        }
#pragma unroll
        for (int i = 0; i < 2; i++)
#pragma unroll
            for (int p = 0; p < 2; p++) {
                float v = dotr[i][p];
                v += __shfl_xor_sync(0xffffffffu, v, 1);
                v += __shfl_xor_sync(0xffffffffu, v, 2);
                if ((lane & 3) == 0) {
                    const int row = bm + wm + i * 16 + crow + p * 8;
                    wpart[(size_t)row * 16 + blockIdx.x * 4 + (wid >> 1)] = v;
                }
            }
        return;
    }

#pragma unroll
    for (int i = 0; i < 2; i++) {
        const int r0 = bm + wm + i * 16 + crow;
#pragma unroll
        for (int j = 0; j < 4; j++) {
            const int col = bn + wn + j * 8 + ccol;
            float bx = 0.f, by = 0.f;
            if (HASBIAS) {
                float2 bv = *(const float2*)(bias + col);
                bx = bv.x; by = bv.y;
            }
            float2 o0, o1;
            o0.x = acc[i][j][0] + bx; o0.y = acc[i][j][1] + by;
            o1.x = acc[i][j][2] + bx; o1.y = acc[i][j][3] + by;
            if (RELU) {
                o0.x = fmaxf(o0.x, 0.f); o0.y = fmaxf(o0.y, 0.f);
                o1.x = fmaxf(o1.x, 0.f); o1.y = fmaxf(o1.y, 0.f);
            }
            if (OUT_HL) {
                __nv_bfloat162 h2, l2;
                split_bf16(o0.x, h2.x, l2.x); split_bf16(o0.y, h2.y, l2.y);
                *(__nv_bfloat162*)(Ch + (size_t)r0 * DD + col) = h2;
                *(__nv_bfloat162*)(Cl + (size_t)r0 * DD + col) = l2;
                split_bf16(o1.x, h2.x, l2.x); split_bf16(o1.y, h2.y, l2.y);
                *(__nv_bfloat162*)(Ch + (size_t)(r0 + 8) * DD + col) = h2;
                *(__nv_bfloat162*)(Cl + (size_t)(r0 + 8) * DD + col) = l2;
            } else {
                *(float2*)(C + (size_t)r0 * DD + col) = o0;
                *(float2*)(C + (size_t)(r0 + 8) * DD + col) = o1;
            }
        }
    }
}

// ---------------------------------------------------------------------------
// Downsample: vds[s,:] = sum_f w[4s+f] * value[4s+f,:]; sw[s] = sum_f w.
// ---------------------------------------------------------------------------
__global__ void __launch_bounds__(256) wds_kernel(
    const float* __restrict__ wpart, const float* __restrict__ value,
    __nv_bfloat16* __restrict__ vh, __nv_bfloat16* __restrict__ vl,
    float* __restrict__ sw)
{
    const int s = blockIdx.x;
    const int tid = threadIdx.x;
    __shared__ float wp[64];
    __shared__ float wf[4];
    if (tid < 64) wp[tid] = wpart[(size_t)s * 64 + tid];
    __syncthreads();
    if (tid < 4) {
        float a = 0.f;
#pragma unroll
        for (int p = 0; p < 16; p++) a += wp[tid * 16 + p];
        wf[tid] = a;
    }
    __syncthreads();
    const float w0 = wf[0], w1 = wf[1], w2 = wf[2], w3 = wf[3];
    if (tid == 0) sw[s] = w0 + w1 + w2 + w3;

    const float* vr = value + (size_t)s * 4 * DD;
    const size_t o = (size_t)s * DD;
#pragma unroll
    for (int u = 0; u < 2; u++) {
        const int d = tid + u * 256;
        float x = w0 * vr[d] + w1 * vr[DD + d] + w2 * vr[2 * DD + d] + w3 * vr[3 * DD + d];
        __nv_bfloat16 h, l;
        split_bf16(x, h, l);
        vh[o + d] = h;
        vl[o + d] = l;
    }
}

// ---------------------------------------------------------------------------
// warp reduction
// ---------------------------------------------------------------------------
__device__ __forceinline__ float warp_sum(float x) {
#pragma unroll
    for (int o = 16; o > 0; o >>= 1) x += __shfl_xor_sync(0xffffffffu, x, o);
    return x;
}

// ---------------------------------------------------------------------------
// LN1: r = q + ao + sw*b_v; out1 = LN(r) (fp32 + bf16 hi/lo)
// ---------------------------------------------------------------------------
__global__ void __launch_bounds__(256) attn_ln_kernel(
    const float* __restrict__ q, const float* __restrict__ ao,
    const float* __restrict__ sw, const float* __restrict__ bv,
    const float* __restrict__ gamma, const float* __restrict__ beta,
    float* __restrict__ out,
    __nv_bfloat16* __restrict__ outh, __nv_bfloat16* __restrict__ outl)
{
    const int row = blockIdx.x;
    const int tid = threadIdx.x;
    const int lane = tid & 31, wid = tid >> 5;
    const size_t off = (size_t)row * DD;
    const float swv = sw[row];

    float r0 = q[off + tid]       + ao[off + tid]       + swv * bv[tid];
    float r1 = q[off + tid + 256] + ao[off + tid + 256] + swv * bv[tid + 256];

    float s = warp_sum(r0 + r1);
    float ss = warp_sum(r0 * r0 + r1 * r1);
    __shared__ float rs[8], rss[8];
    if (lane == 0) { rs[wid] = s; rss[wid] = ss; }
    __syncthreads();
    __shared__ float mv[2];
    if (tid == 0) {
        float S = 0.f, SS = 0.f;
#pragma unroll
        for (int i = 0; i < 8; i++) { S += rs[i]; SS += rss[i]; }
        float mean = S * (1.f / 512.f);
        float var = SS * (1.f / 512.f) - mean * mean;
        mv[0] = mean; mv[1] = rsqrtf(var + EPS);
    }
    __syncthreads();
    const float mean = mv[0], inv = mv[1];
    float y0 = (r0 - mean) * inv * gamma[tid]       + beta[tid];
    float y1 = (r1 - mean) * inv * gamma[tid + 256] + beta[tid + 256];
    out[off + tid] = y0;
    out[off + tid + 256] = y1;
    __nv_bfloat16 h, l;
    split_bf16(y0, h, l); outh[off + tid] = h;       outl[off + tid] = l;
    split_bf16(y1, h, l); outh[off + tid + 256] = h; outl[off + tid + 256] = l;
}

// ---------------------------------------------------------------------------
// Fused residual + LayerNorm2 -> output
// ---------------------------------------------------------------------------
__global__ void __launch_bounds__(256) resid_ln_kernel(
    const float* __restrict__ a, const float* __restrict__ f,
    const float* __restrict__ gamma, const float* __restrict__ beta,
    float* __restrict__ out)
{
    const int row = blockIdx.x;
    const int tid = threadIdx.x;
    const int lane = tid & 31, wid = tid >> 5;
    const size_t off = (size_t)row * DD;

    float r0 = a[off + tid]       + f[off + tid];
    float r1 = a[off + tid + 256] + f[off + tid + 256];

    float s = warp_sum(r0 + r1);
    float ss = warp_sum(r0 * r0 + r1 * r1);
    __shared__ float rs[8], rss[8];
    if (lane == 0) { rs[wid] = s; rss[wid] = ss; }
    __syncthreads();
    __shared__ float mv[2];
    if (tid == 0) {
        float S = 0.f, SS = 0.f;
#pragma unroll
        for (int i = 0; i < 8; i++) { S += rs[i]; SS += rss[i]; }
        float mean = S * (1.f / 512.f);
        float var = SS * (1.f / 512.f) - mean * mean;
        mv[0] = mean; mv[1] = rsqrtf(var + EPS);
    }
    __syncthreads();
    const float mean = mv[0], inv = mv[1];
    out[off + tid]       = (r0 - mean) * inv * gamma[tid]       + beta[tid];
    out[off + tid + 256] = (r1 - mean) * inv * gamma[tid + 256] + beta[tid + 256];
}

// ---------------------------------------------------------------------------
// Launch
// ---------------------------------------------------------------------------
extern "C" void kernel_launch(void* const* d_in, const int* in_sizes, int n_in,
                              void* d_out, int out_size)
{
    const float* query  = (const float*)d_in[0];
    const float* key    = (const float*)d_in[1];
    const float* value  = (const float*)d_in[2];
    const float* w_q    = (const float*)d_in[3];
    const float* b_q    = (const float*)d_in[4];
    const float* w_k    = (const float*)d_in[5];
    const float* b_k    = (const float*)d_in[6];
    const float* w_v    = (const float*)d_in[7];
    const float* b_v    = (const float*)d_in[8];
    const float* ln1_g  = (const float*)d_in[9];
    const float* ln1_b  = (const float*)d_in[10];
    const float* ln2_g  = (const float*)d_in[11];
    const float* ln2_b  = (const float*)d_in[12];
    const float* ffn_w1 = (const float*)d_in[13];
    const float* ffn_b1 = (const float*)d_in[14];
    const float* ffn_w2 = (const float*)d_in[15];
    const float* ffn_b2 = (const float*)d_in[16];
    float* out = (float*)d_out;

    void* sp = nullptr;
    cudaGetSymbolAddress(&sp, g_scratch);
    float* s = (float*)sp;
    float* g_q    = s + F_Q;
    float* g_ao   = s + F_AO;
    float* g_out1 = s + F_O1;
    float* g_ffn  = s + F_FF;
    float* g_wp   = s + F_WP;
    float* g_sw   = s + F_SW;

    void* ap = nullptr;
    cudaGetSymbolAddress(&ap, g_act);
    __nv_bfloat16* a = (__nv_bfloat16*)ap;
    __nv_bfloat16* qh  = a + B_QH;  __nv_bfloat16* ql  = a + B_QL;
    __nv_bfloat16* kh  = a + B_KH;  __nv_bfloat16* kl  = a + B_KL;
    __nv_bfloat16* vh  = a + B_VH;  __nv_bfloat16* vl  = a + B_VL;
    __nv_bfloat16* o1h = a + B_O1H; __nv_bfloat16* o1l = a + B_O1L;
    __nv_bfloat16* hh  = a + B_HH;  __nv_bfloat16* hl  = a + B_HL;

    void* wp = nullptr;
    cudaGetSymbolAddress(&wp, g_wsplit);
    __nv_bfloat16* w = (__nv_bfloat16*)wp;
    const size_t WSZ = 512u * 512u;
    __nv_bfloat16* wqh = w + 0 * 2 * WSZ; __nv_bfloat16* wql = wqh + WSZ;
    __nv_bfloat16* wkh = w + 1 * 2 * WSZ; __nv_bfloat16* wkl = wkh + WSZ;
    __nv_bfloat16* wvh = w + 2 * 2 * WSZ; __nv_bfloat16* wvl = wvh + WSZ;
    __nv_bfloat16* f1h = w + 3 * 2 * WSZ; __nv_bfloat16* f1l = f1h + WSZ;
    __nv_bfloat16* f2h = w + 4 * 2 * WSZ; __nv_bfloat16* f2l = f2h + WSZ;

    cudaFuncSetAttribute((const void*)gemm_hl<true,  false, false, true >, cudaFuncAttributeMaxDynamicSharedMemorySize, GEMM_SMEM);
    cudaFuncSetAttribute((const void*)gemm_hl<true,  false, true,  true >, cudaFuncAttributeMaxDynamicSharedMemorySize, GEMM_SMEM);
    cudaFuncSetAttribute((const void*)gemm_hl<false, false, false, false>, cudaFuncAttributeMaxDynamicSharedMemorySize, GEMM_SMEM);
    cudaFuncSetAttribute((const void*)gemm_hl<true,  true,  false, true >, cudaFuncAttributeMaxDynamicSharedMemorySize, GEMM_SMEM);
    cudaFuncSetAttribute((const void*)gemm_hl<false, false, false, true >, cudaFuncAttributeMaxDynamicSharedMemorySize, GEMM_SMEM);

    const dim3 blk(256);

    prep_weight5<<<dim3(16, 16, 5), dim3(32, 8)>>>(w_q, w_k, w_v, ffn_w1, ffn_w2, w);
    f32_to_hl<<<NQ  * DD / 1024, blk>>>((const float4*)query, (uint2*)qh, (uint2*)ql);
    f32_to_hl<<<NKV * DD / 1024, blk>>>((const float4*)key,   (uint2*)kh, (uint2*)kl);

    const dim3 grid_q(DD / 128, NQ / 64);   // 4 x 128
    const dim3 grid_kv(DD / 128, NKV / 64); // 4 x 512

    // Q projection
    gemm_hl<true, false, false, true><<<grid_q, blk, GEMM_SMEM>>>(
        qh, ql, wqh, wql, b_q, g_q, nullptr, nullptr, nullptr, nullptr);

    // K projection with fused q.k dot -> w partials
    gemm_hl<true, false, true, true><<<grid_kv, blk, GEMM_SMEM>>>(
        kh, kl, wkh, wkl, b_k, nullptr, nullptr, nullptr, g_q, g_wp);

    // downsample raw value by w
    wds_kernel<<<NQ, blk>>>(g_wp, value, vh, vl, g_sw);

    // V projection on downsampled rows
    gemm_hl<false, false, false, false><<<grid_q, blk, GEMM_SMEM>>>(
        vh, vl, wvh, wvl, nullptr, g_ao, nullptr, nullptr, nullptr, nullptr);

    // LN1
    attn_ln_kernel<<<NQ, blk>>>(g_q, g_ao, g_sw, b_v, ln1_g, ln1_b, g_out1, o1h, o1l);

    // FFN
    gemm_hl<true, true, false, true><<<grid_q, blk, GEMM_SMEM>>>(
        o1h, o1l, f1h, f1l, ffn_b1, nullptr, hh, hl, nullptr, nullptr);
    gemm_hl<false, false, false, true><<<grid_q, blk, GEMM_SMEM>>>(
        hh, hl, f2h, f2l, ffn_b2, g_ffn, nullptr, nullptr, nullptr, nullptr);

    resid_ln_kernel<<<NQ, blk>>>(g_out1, g_ffn, ln2_g, ln2_b, out);
}

// round 10
// speedup vs baseline: 1.0008x; 1.0008x over previous
#include <cuda_runtime.h>
#include <cuda_bf16.h>
#include <cstdint>

// ---------------------------------------------------------------------------
// AttentionSampling: B=4, SQ=2048, SK=8192, D=H=512, F=4, fp32.
// GEMMs via mma.sync bf16 hi/lo 3-pass. Round 10: R8 geometry (128x128,
// 3-stage, 2 CTAs/SM, XOR swizzle, 1 barrier/chunk) + cp.async issued in
// the LDSM shadow so HMMAs restart immediately after each barrier.
// ---------------------------------------------------------------------------

#define DD 512
#define NQ  8192
#define NKV 32768
#define EPS 1e-5f

// fp32 scratch planes
#define F_Q   0
#define F_AO  (F_Q  + (size_t)NQ * DD)
#define F_O1  (F_AO + (size_t)NQ * DD)
#define F_FF  (F_O1 + (size_t)NQ * DD)
#define F_WP  (F_FF + (size_t)NQ * DD)          // w_part [NKV][16]
#define F_SW  (F_WP + (size_t)NKV * 16)         // sum-of-w [NQ]
#define F_TOT (F_SW + (size_t)NQ)
__device__ float g_scratch[F_TOT];

// bf16 hi/lo activation planes
#define B_QH  0
#define B_QL  (B_QH  + (size_t)NQ  * DD)
#define B_KH  (B_QL  + (size_t)NQ  * DD)
#define B_KL  (B_KH  + (size_t)NKV * DD)
#define B_VH  (B_KL  + (size_t)NKV * DD)        // downsampled value (NQ rows)
#define B_VL  (B_VH  + (size_t)NQ  * DD)
#define B_O1H (B_VL  + (size_t)NQ  * DD)
#define B_O1L (B_O1H + (size_t)NQ  * DD)
#define B_HH  (B_O1L + (size_t)NQ  * DD)
#define B_HL  (B_HH  + (size_t)NQ  * DD)
#define B_TOT (B_HL  + (size_t)NQ  * DD)
__device__ __nv_bfloat16 g_act[B_TOT];

// 5 weights x (hi,lo) x 512x512 bf16, stored [N][K] (transposed)
__device__ __nv_bfloat16 g_wsplit[5u * 2u * 512u * 512u];

// ---------------------------------------------------------------------------
// PTX helpers (base sm_100-legal)
// ---------------------------------------------------------------------------
__device__ __forceinline__ uint32_t smem_u32(const void* p) {
    uint32_t a;
    asm("{ .reg .u64 t; cvta.to.shared.u64 t, %1; cvt.u32.u64 %0, t; }"
        : "=r"(a) : "l"(p));
    return a;
}
__device__ __forceinline__ void ldsm_x4(uint32_t* r, uint32_t addr) {
    asm volatile("ldmatrix.sync.aligned.m8n8.x4.shared.b16 {%0,%1,%2,%3}, [%4];"
                 : "=r"(r[0]), "=r"(r[1]), "=r"(r[2]), "=r"(r[3]) : "r"(addr));
}
__device__ __forceinline__ void mma16816(float* c, const uint32_t* a, const uint32_t* b) {
    asm volatile(
        "mma.sync.aligned.m16n8k16.row.col.f32.bf16.bf16.f32 "
        "{%0,%1,%2,%3}, {%4,%5,%6,%7}, {%8,%9}, {%0,%1,%2,%3};"
        : "+f"(c[0]), "+f"(c[1]), "+f"(c[2]), "+f"(c[3])
        : "r"(a[0]), "r"(a[1]), "r"(a[2]), "r"(a[3]), "r"(b[0]), "r"(b[1]));
}
__device__ __forceinline__ void cp16(uint32_t saddr, const void* g) {
    asm volatile("cp.async.cg.shared.global [%0], [%1], 16;"
                 :: "r"(saddr), "l"(g) : "memory");
}
__device__ __forceinline__ void cp_commit() {
    asm volatile("cp.async.commit_group;" ::: "memory");
}
__device__ __forceinline__ void split_bf16(float x, __nv_bfloat16& h, __nv_bfloat16& l) {
    h = __float2bfloat16(x);
    l = __float2bfloat16(x - __bfloat162float(h));
}

// swizzled byte offset of 16B chunk (row, chunk) in a 128x64B plane
__device__ __forceinline__ uint32_t swz_off(uint32_t row, uint32_t chunk) {
    return row * 64u + ((chunk ^ ((row >> 1) & 3u)) << 4);
}

// ---------------------------------------------------------------------------
// Batched weight prep: W[k][n] fp32 -> Th[n][k], Tl[n][k] bf16 (5 weights)
// ---------------------------------------------------------------------------
__global__ void prep_weight5(
    const float* w0, const float* w1, const float* w2, const float* w3, const float* w4,
    __nv_bfloat16* base)
{
    const float* Ws[5] = {w0, w1, w2, w3, w4};
    const size_t WSZ = 512u * 512u;
    const float* W = Ws[blockIdx.z];
    __nv_bfloat16* Th = base + (size_t)blockIdx.z * 2u * WSZ;
    __nv_bfloat16* Tl = Th + WSZ;

    __shared__ float t[32][33];
    const int bx = blockIdx.x * 32, by = blockIdx.y * 32;
    const int tx = threadIdx.x, ty = threadIdx.y; // 32 x 8
#pragma unroll
    for (int i = 0; i < 32; i += 8)
        t[ty + i][tx] = W[(size_t)(by + ty + i) * DD + bx + tx];
    __syncthreads();
#pragma unroll
    for (int i = 0; i < 32; i += 8) {
        float x = t[tx][ty + i];
        __nv_bfloat16 h, l;
        split_bf16(x, h, l);
        size_t o = (size_t)(bx + ty + i) * DD + by + tx;
        Th[o] = h;
        Tl[o] = l;
    }
}

// ---------------------------------------------------------------------------
// fp32 -> bf16 hi/lo split (vectorized)
// ---------------------------------------------------------------------------
__global__ void __launch_bounds__(256) f32_to_hl(
    const float4* __restrict__ src, uint2* __restrict__ dh, uint2* __restrict__ dl)
{
    const int i = blockIdx.x * 256 + threadIdx.x;
    float4 x = src[i];
    __nv_bfloat16 hx, hy, hz, hw, lx, ly, lz, lw;
    split_bf16(x.x, hx, lx); split_bf16(x.y, hy, ly);
    split_bf16(x.z, hz, lz); split_bf16(x.w, hw, lw);
    __nv_bfloat162 h01, h23, l01, l23;
    h01.x = hx; h01.y = hy; h23.x = hz; h23.y = hw;
    l01.x = lx; l01.y = ly; l23.x = lz; l23.y = lw;
    uint2 hv, lv;
    hv.x = *(uint32_t*)&h01; hv.y = *(uint32_t*)&h23;
    lv.x = *(uint32_t*)&l01; lv.y = *(uint32_t*)&l23;
    dh[i] = hv;
    dl[i] = lv;
}

// ---------------------------------------------------------------------------
// HMMA GEMM: act(A[M,512] @ W[512,512] + bias)
// BM=128, BN=128, BK=32, 256 thr (8 warps 2m x 4n; warp tile 64x32).
// 3-stage cp.async pipeline, XOR-swizzled 64B rows, 1 barrier/chunk,
// launch_bounds(256,2) -> 2 CTAs/SM. Loads issued in LDSM shadow.
// DOTQ: k rows dotted with q rows instead of stored (w partials out).
// ---------------------------------------------------------------------------
#define BKC 32
#define NCH (DD / BKC)          // 16
#define PLANE 8192              // 128 rows x 64B, swizzled
#define SG_AH 0
#define SG_AL (1 * PLANE)
#define SG_BH (2 * PLANE)
#define SG_BL (3 * PLANE)
#define SG_SZ (4 * PLANE)       // 32768
#define STAGES 3
#define GEMM_SMEM (STAGES * SG_SZ) // 98304

template <bool RELU, bool OUT_HL, bool DOTQ, bool HASBIAS>
__global__ void __launch_bounds__(256, 2) gemm_hl(
    const __nv_bfloat16* __restrict__ Ah, const __nv_bfloat16* __restrict__ Al,
    const __nv_bfloat16* __restrict__ Bh, const __nv_bfloat16* __restrict__ Bl,
    const float* __restrict__ bias, float* __restrict__ C,
    __nv_bfloat16* __restrict__ Ch, __nv_bfloat16* __restrict__ Cl,
    const float* __restrict__ qdot, float* __restrict__ wpart)
{
    extern __shared__ char sm[];
    const uint32_t sb = smem_u32(sm);

    const int tid = threadIdx.x;
    const int lane = tid & 31, wid = tid >> 5;
    const int wm = (wid & 1) * 64;
    const int wn = (wid >> 1) * 32;
    const int bm = blockIdx.y * 128;
    const int bn = blockIdx.x * 128;

    float acc[4][4][4];
#pragma unroll
    for (int i = 0; i < 4; i++)
#pragma unroll
        for (int j = 0; j < 4; j++)
#pragma unroll
            for (int t = 0; t < 4; t++) acc[i][j][t] = 0.f;

    const uint32_t row0 = (uint32_t)(tid >> 2), seg0 = (uint32_t)(tid & 3);
    const uint32_t row1 = row0 + 64;

    auto load_stage = [&](int c, int buf) {
        const uint32_t st = sb + buf * SG_SZ;
        const int kc = c * BKC;
        {
            uint32_t so = swz_off(row0, seg0);
            size_t ga = (size_t)(bm + row0) * DD + kc + seg0 * 8;
            size_t gb = (size_t)(bn + row0) * DD + kc + seg0 * 8;
            cp16(st + SG_AH + so, Ah + ga);
            cp16(st + SG_AL + so, Al + ga);
            cp16(st + SG_BH + so, Bh + gb);
            cp16(st + SG_BL + so, Bl + gb);
        }
        {
            uint32_t so = swz_off(row1, seg0);
            size_t ga = (size_t)(bm + row1) * DD + kc + seg0 * 8;
            size_t gb = (size_t)(bn + row1) * DD + kc + seg0 * 8;
            cp16(st + SG_AH + so, Ah + ga);
            cp16(st + SG_AL + so, Al + ga);
            cp16(st + SG_BH + so, Bh + gb);
            cp16(st + SG_BL + so, Bl + gb);
        }
        cp_commit();
    };

    const uint32_t a_r = (uint32_t)(wm + (lane & 15));
    const uint32_t a_ch = (uint32_t)(lane >> 4);        // chunk half (0/1)
    const uint32_t b_r = (uint32_t)(wn + ((lane >> 4) << 3) + (lane & 7));
    const uint32_t b_ch = (uint32_t)((lane >> 3) & 1);

    // one chunk of compute; next-stage load issued inside the ks=0 LDSM shadow
    auto compute_chunk = [&](int buf, bool do_load, int lc, int lbuf) {
        const uint32_t st = sb + buf * SG_SZ;
        // ---- ks = 0 ----
        {
            uint32_t ah[4][4], al[4][4], bh[2][4], bl[2][4];
#pragma unroll
            for (int i = 0; i < 4; i++) {
                uint32_t off = swz_off(a_r + i * 16, a_ch);
                ldsm_x4(ah[i], st + SG_AH + off);
                ldsm_x4(al[i], st + SG_AL + off);
            }
#pragma unroll
            for (int jp = 0; jp < 2; jp++) {
                uint32_t off = swz_off(b_r + jp * 16, b_ch);
                ldsm_x4(bh[jp], st + SG_BH + off);
                ldsm_x4(bl[jp], st + SG_BL + off);
            }
            // issue next-stage cp.async while LDSM results are in flight
            if (do_load) load_stage(lc, lbuf);
#pragma unroll
            for (int i = 0; i < 4; i++)
#pragma unroll
                for (int j = 0; j < 4; j++)
                    mma16816(acc[i][j], ah[i], &bh[j >> 1][(j & 1) * 2]);
#pragma unroll
            for (int i = 0; i < 4; i++)
#pragma unroll
                for (int j = 0; j < 4; j++)
                    mma16816(acc[i][j], ah[i], &bl[j >> 1][(j & 1) * 2]);
#pragma unroll
            for (int i = 0; i < 4; i++)
#pragma unroll
                for (int j = 0; j < 4; j++)
                    mma16816(acc[i][j], al[i], &bh[j >> 1][(j & 1) * 2]);
        }
        // ---- ks = 1 ----
        {
            uint32_t ah[4][4], al[4][4], bh[2][4], bl[2][4];
#pragma unroll
            for (int i = 0; i < 4; i++) {
                uint32_t off = swz_off(a_r + i * 16, 2 + a_ch);
                ldsm_x4(ah[i], st + SG_AH + off);
                ldsm_x4(al[i], st + SG_AL + off);
            }
#pragma unroll
            for (int jp = 0; jp < 2; jp++) {
                uint32_t off = swz_off(b_r + jp * 16, 2 + b_ch);
                ldsm_x4(bh[jp], st + SG_BH + off);
                ldsm_x4(bl[jp], st + SG_BL + off);
            }
#pragma unroll
            for (int i = 0; i < 4; i++)
#pragma unroll
                for (int j = 0; j < 4; j++)
                    mma16816(acc[i][j], ah[i], &bh[j >> 1][(j & 1) * 2]);
#pragma unroll
            for (int i = 0; i < 4; i++)
#pragma unroll
                for (int j = 0; j < 4; j++)
                    mma16816(acc[i][j], ah[i], &bl[j >> 1][(j & 1) * 2]);
#pragma unroll
            for (int i = 0; i < 4; i++)
#pragma unroll
                for (int j = 0; j < 4; j++)
                    mma16816(acc[i][j], al[i], &bh[j >> 1][(j & 1) * 2]);
        }
    };

    // 3-stage pipeline, one barrier per chunk.
    load_stage(0, 0);
    load_stage(1, 1);

#pragma unroll 1
    for (int c = 0; c < NCH; c++) {
        if (c < NCH - 1)
            asm volatile("cp.async.wait_group 1;" ::: "memory");
        else
            asm volatile("cp.async.wait_group 0;" ::: "memory");
        __syncthreads();
        compute_chunk(c % 3, c + 2 < NCH, c + 2, (c + 2) % 3);
    }

    // ---------------- epilogue ----------------
    const int crow = lane >> 2, ccol = (lane & 3) * 2;

    if (DOTQ) {
        float dotr[4][2];
#pragma unroll
        for (int i = 0; i < 4; i++) { dotr[i][0] = 0.f; dotr[i][1] = 0.f; }
#pragma unroll
        for (int i = 0; i < 4; i++) {
            const int r0 = bm + wm + i * 16 + crow;
            const float* q0p = qdot + (size_t)(r0 >> 2) * DD;
            const float* q1p = qdot + (size_t)((r0 + 8) >> 2) * DD;
#pragma unroll
            for (int j = 0; j < 4; j++) {
                const int col = bn + wn + j * 8 + ccol;
                float bx = 0.f, by = 0.f;
                if (HASBIAS) {
                    float2 bv = *(const float2*)(bias + col);
                    bx = bv.x; by = bv.y;
                }
                float k00 = fmaxf(acc[i][j][0] + bx, 0.f);
                float k01 = fmaxf(acc[i][j][1] + by, 0.f);
                float k10 = fmaxf(acc[i][j][2] + bx, 0.f);
                float k11 = fmaxf(acc[i][j][3] + by, 0.f);
                float2 q0 = *(const float2*)(q0p + col);
                float2 q1 = *(const float2*)(q1p + col);
                dotr[i][0] += k00 * q0.x + k01 * q0.y;
                dotr[i][1] += k10 * q1.x + k11 * q1.y;
            }
        }
#pragma unroll
        for (int i = 0; i < 4; i++)
#pragma unroll
            for (int p = 0; p < 2; p++) {
                float v = dotr[i][p];
                v += __shfl_xor_sync(0xffffffffu, v, 1);
                v += __shfl_xor_sync(0xffffffffu, v, 2);
                if ((lane & 3) == 0) {
                    const int row = bm + wm + i * 16 + crow + p * 8;
                    wpart[(size_t)row * 16 + blockIdx.x * 4 + (wid >> 1)] = v;
                }
            }
        return;
    }

#pragma unroll
    for (int i = 0; i < 4; i++) {
        const int r0 = bm + wm + i * 16 + crow;
#pragma unroll
        for (int j = 0; j < 4; j++) {
            const int col = bn + wn + j * 8 + ccol;
            float bx = 0.f, by = 0.f;
            if (HASBIAS) {
                float2 bv = *(const float2*)(bias + col);
                bx = bv.x; by = bv.y;
            }
            float2 o0, o1;
            o0.x = acc[i][j][0] + bx; o0.y = acc[i][j][1] + by;
            o1.x = acc[i][j][2] + bx; o1.y = acc[i][j][3] + by;
            if (RELU) {
                o0.x = fmaxf(o0.x, 0.f); o0.y = fmaxf(o0.y, 0.f);
                o1.x = fmaxf(o1.x, 0.f); o1.y = fmaxf(o1.y, 0.f);
            }
            if (OUT_HL) {
                __nv_bfloat162 h2, l2;
                split_bf16(o0.x, h2.x, l2.x); split_bf16(o0.y, h2.y, l2.y);
                *(__nv_bfloat162*)(Ch + (size_t)r0 * DD + col) = h2;
                *(__nv_bfloat162*)(Cl + (size_t)r0 * DD + col) = l2;
                split_bf16(o1.x, h2.x, l2.x); split_bf16(o1.y, h2.y, l2.y);
                *(__nv_bfloat162*)(Ch + (size_t)(r0 + 8) * DD + col) = h2;
                *(__nv_bfloat162*)(Cl + (size_t)(r0 + 8) * DD + col) = l2;
            } else {
                *(float2*)(C + (size_t)r0 * DD + col) = o0;
                *(float2*)(C + (size_t)(r0 + 8) * DD + col) = o1;
            }
        }
    }
}

// ---------------------------------------------------------------------------
// Downsample: vds[s,:] = sum_f w[4s+f] * value[4s+f,:]; sw[s] = sum_f w.
// ---------------------------------------------------------------------------
__global__ void __launch_bounds__(256) wds_kernel(
    const float* __restrict__ wpart, const float* __restrict__ value,
    __nv_bfloat16* __restrict__ vh, __nv_bfloat16* __restrict__ vl,
    float* __restrict__ sw)
{
    const int s = blockIdx.x;
    const int tid = threadIdx.x;
    __shared__ float wp[64];
    __shared__ float wf[4];
    if (tid < 64) wp[tid] = wpart[(size_t)s * 64 + tid];
    __syncthreads();
    if (tid < 4) {
        float a = 0.f;
#pragma unroll
        for (int p = 0; p < 16; p++) a += wp[tid * 16 + p];
        wf[tid] = a;
    }
    __syncthreads();
    const float w0 = wf[0], w1 = wf[1], w2 = wf[2], w3 = wf[3];
    if (tid == 0) sw[s] = w0 + w1 + w2 + w3;

    const float* vr = value + (size_t)s * 4 * DD;
    const size_t o = (size_t)s * DD;
#pragma unroll
    for (int u = 0; u < 2; u++) {
        const int d = tid + u * 256;
        float x = w0 * vr[d] + w1 * vr[DD + d] + w2 * vr[2 * DD + d] + w3 * vr[3 * DD + d];
        __nv_bfloat16 h, l;
        split_bf16(x, h, l);
        vh[o + d] = h;
        vl[o + d] = l;
    }
}

// ---------------------------------------------------------------------------
// warp reduction
// ---------------------------------------------------------------------------
__device__ __forceinline__ float warp_sum(float x) {
#pragma unroll
    for (int o = 16; o > 0; o >>= 1) x += __shfl_xor_sync(0xffffffffu, x, o);
    return x;
}

// ---------------------------------------------------------------------------
// LN1: r = q + ao + sw*b_v; out1 = LN(r) (fp32 + bf16 hi/lo)
// ---------------------------------------------------------------------------
__global__ void __launch_bounds__(256) attn_ln_kernel(
    const float* __restrict__ q, const float* __restrict__ ao,
    const float* __restrict__ sw, const float* __restrict__ bv,
    const float* __restrict__ gamma, const float* __restrict__ beta,
    float* __restrict__ out,
    __nv_bfloat16* __restrict__ outh, __nv_bfloat16* __restrict__ outl)
{
    const int row = blockIdx.x;
    const int tid = threadIdx.x;
    const int lane = tid & 31, wid = tid >> 5;
    const size_t off = (size_t)row * DD;
    const float swv = sw[row];

    float r0 = q[off + tid]       + ao[off + tid]       + swv * bv[tid];
    float r1 = q[off + tid + 256] + ao[off + tid + 256] + swv * bv[tid + 256];

    float s = warp_sum(r0 + r1);
    float ss = warp_sum(r0 * r0 + r1 * r1);
    __shared__ float rs[8], rss[8];
    if (lane == 0) { rs[wid] = s; rss[wid] = ss; }
    __syncthreads();
    __shared__ float mv[2];
    if (tid == 0) {
        float S = 0.f, SS = 0.f;
#pragma unroll
        for (int i = 0; i < 8; i++) { S += rs[i]; SS += rss[i]; }
        float mean = S * (1.f / 512.f);
        float var = SS * (1.f / 512.f) - mean * mean;
        mv[0] = mean; mv[1] = rsqrtf(var + EPS);
    }
    __syncthreads();
    const float mean = mv[0], inv = mv[1];
    float y0 = (r0 - mean) * inv * gamma[tid]       + beta[tid];
    float y1 = (r1 - mean) * inv * gamma[tid + 256] + beta[tid + 256];
    out[off + tid] = y0;
    out[off + tid + 256] = y1;
    __nv_bfloat16 h, l;
    split_bf16(y0, h, l); outh[off + tid] = h;       outl[off + tid] = l;
    split_bf16(y1, h, l); outh[off + tid + 256] = h; outl[off + tid + 256] = l;
}

// ---------------------------------------------------------------------------
// Fused residual + LayerNorm2 -> output
// ---------------------------------------------------------------------------
__global__ void __launch_bounds__(256) resid_ln_kernel(
    const float* __restrict__ a, const float* __restrict__ f,
    const float* __restrict__ gamma, const float* __restrict__ beta,
    float* __restrict__ out)
{
    const int row = blockIdx.x;
    const int tid = threadIdx.x;
    const int lane = tid & 31, wid = tid >> 5;
    const size_t off = (size_t)row * DD;

    float r0 = a[off + tid]       + f[off + tid];
    float r1 = a[off + tid + 256] + f[off + tid + 256];

    float s = warp_sum(r0 + r1);
    float ss = warp_sum(r0 * r0 + r1 * r1);
    __shared__ float rs[8], rss[8];
    if (lane == 0) { rs[wid] = s; rss[wid] = ss; }
    __syncthreads();
    __shared__ float mv[2];
    if (tid == 0) {
        float S = 0.f, SS = 0.f;
#pragma unroll
        for (int i = 0; i < 8; i++) { S += rs[i]; SS += rss[i]; }
        float mean = S * (1.f / 512.f);
        float var = SS * (1.f / 512.f) - mean * mean;
        mv[0] = mean; mv[1] = rsqrtf(var + EPS);
    }
    __syncthreads();
    const float mean = mv[0], inv = mv[1];
    out[off + tid]       = (r0 - mean) * inv * gamma[tid]       + beta[tid];
    out[off + tid + 256] = (r1 - mean) * inv * gamma[tid + 256] + beta[tid + 256];
}

// ---------------------------------------------------------------------------
// Launch
// ---------------------------------------------------------------------------
extern "C" void kernel_launch(void* const* d_in, const int* in_sizes, int n_in,
                              void* d_out, int out_size)
{
    const float* query  = (const float*)d_in[0];
    const float* key    = (const float*)d_in[1];
    const float* value  = (const float*)d_in[2];
    const float* w_q    = (const float*)d_in[3];
    const float* b_q    = (const float*)d_in[4];
    const float* w_k    = (const float*)d_in[5];
    const float* b_k    = (const float*)d_in[6];
    const float* w_v    = (const float*)d_in[7];
    const float* b_v    = (const float*)d_in[8];
    const float* ln1_g  = (const float*)d_in[9];
    const float* ln1_b  = (const float*)d_in[10];
    const float* ln2_g  = (const float*)d_in[11];
    const float* ln2_b  = (const float*)d_in[12];
    const float* ffn_w1 = (const float*)d_in[13];
    const float* ffn_b1 = (const float*)d_in[14];
    const float* ffn_w2 = (const float*)d_in[15];
    const float* ffn_b2 = (const float*)d_in[16];
    float* out = (float*)d_out;

    void* sp = nullptr;
    cudaGetSymbolAddress(&sp, g_scratch);
    float* s = (float*)sp;
    float* g_q    = s + F_Q;
    float* g_ao   = s + F_AO;
    float* g_out1 = s + F_O1;
    float* g_ffn  = s + F_FF;
    float* g_wp   = s + F_WP;
    float* g_sw   = s + F_SW;

    void* ap = nullptr;
    cudaGetSymbolAddress(&ap, g_act);
    __nv_bfloat16* a = (__nv_bfloat16*)ap;
    __nv_bfloat16* qh  = a + B_QH;  __nv_bfloat16* ql  = a + B_QL;
    __nv_bfloat16* kh  = a + B_KH;  __nv_bfloat16* kl  = a + B_KL;
    __nv_bfloat16* vh  = a + B_VH;  __nv_bfloat16* vl  = a + B_VL;
    __nv_bfloat16* o1h = a + B_O1H; __nv_bfloat16* o1l = a + B_O1L;
    __nv_bfloat16* hh  = a + B_HH;  __nv_bfloat16* hl  = a + B_HL;

    void* wp = nullptr;
    cudaGetSymbolAddress(&wp, g_wsplit);
    __nv_bfloat16* w = (__nv_bfloat16*)wp;
    const size_t WSZ = 512u * 512u;
    __nv_bfloat16* wqh = w + 0 * 2 * WSZ; __nv_bfloat16* wql = wqh + WSZ;
    __nv_bfloat16* wkh = w + 1 * 2 * WSZ; __nv_bfloat16* wkl = wkh + WSZ;
    __nv_bfloat16* wvh = w + 2 * 2 * WSZ; __nv_bfloat16* wvl = wvh + WSZ;
    __nv_bfloat16* f1h = w + 3 * 2 * WSZ; __nv_bfloat16* f1l = f1h + WSZ;
    __nv_bfloat16* f2h = w + 4 * 2 * WSZ; __nv_bfloat16* f2l = f2h + WSZ;

    cudaFuncSetAttribute((const void*)gemm_hl<true,  false, false, true >, cudaFuncAttributeMaxDynamicSharedMemorySize, GEMM_SMEM);
    cudaFuncSetAttribute((const void*)gemm_hl<true,  false, true,  true >, cudaFuncAttributeMaxDynamicSharedMemorySize, GEMM_SMEM);
    cudaFuncSetAttribute((const void*)gemm_hl<false, false, false, false>, cudaFuncAttributeMaxDynamicSharedMemorySize, GEMM_SMEM);
    cudaFuncSetAttribute((const void*)gemm_hl<true,  true,  false, true >, cudaFuncAttributeMaxDynamicSharedMemorySize, GEMM_SMEM);
    cudaFuncSetAttribute((const void*)gemm_hl<false, false, false, true >, cudaFuncAttributeMaxDynamicSharedMemorySize, GEMM_SMEM);

    const dim3 blk(256);

    prep_weight5<<<dim3(16, 16, 5), dim3(32, 8)>>>(w_q, w_k, w_v, ffn_w1, ffn_w2, w);
    f32_to_hl<<<NQ  * DD / 1024, blk>>>((const float4*)query, (uint2*)qh, (uint2*)ql);
    f32_to_hl<<<NKV * DD / 1024, blk>>>((const float4*)key,   (uint2*)kh, (uint2*)kl);

    const dim3 grid_q(DD / 128, NQ / 128);   // 4 x 64
    const dim3 grid_kv(DD / 128, NKV / 128); // 4 x 256

    // Q projection
    gemm_hl<true, false, false, true><<<grid_q, blk, GEMM_SMEM>>>(
        qh, ql, wqh, wql, b_q, g_q, nullptr, nullptr, nullptr, nullptr);

    // K projection with fused q.k dot -> w partials
    gemm_hl<true, false, true, true><<<grid_kv, blk, GEMM_SMEM>>>(
        kh, kl, wkh, wkl, b_k, nullptr, nullptr, nullptr, g_q, g_wp);

    // downsample raw value by w
    wds_kernel<<<NQ, blk>>>(g_wp, value, vh, vl, g_sw);

    // V projection on downsampled rows
    gemm_hl<false, false, false, false><<<grid_q, blk, GEMM_SMEM>>>(
        vh, vl, wvh, wvl, nullptr, g_ao, nullptr, nullptr, nullptr, nullptr);

    // LN1
    attn_ln_kernel<<<NQ, blk>>>(g_q, g_ao, g_sw, b_v, ln1_g, ln1_b, g_out1, o1h, o1l);

    // FFN
    gemm_hl<true, true, false, true><<<grid_q, blk, GEMM_SMEM>>>(
        o1h, o1l, f1h, f1l, ffn_b1, nullptr, hh, hl, nullptr, nullptr);
    gemm_hl<false, false, false, true><<<grid_q, blk, GEMM_SMEM>>>(
        hh, hl, f2h, f2l, ffn_b2, g_ffn, nullptr, nullptr, nullptr, nullptr);

    resid_ln_kernel<<<NQ, blk>>>(g_out1, g_ffn, ln2_g, ln2_b, out);
}

// round 11
// speedup vs baseline: 1.3554x; 1.3544x over previous
#include <cuda_runtime.h>
#include <cuda_bf16.h>
#include <cuda_fp16.h>
#include <cstdint>

// ---------------------------------------------------------------------------
// AttentionSampling: B=4, SQ=2048, SK=8192, D=H=512, F=4, fp32.
// Round 11: fp16 scaled-split GEMMs. A = single fp16 plane (err 2^-12);
// W = fp16 hi/lo pre-scaled by 4096 (lo stays normal-range); 2 MMA passes,
// acc * (1/4096) in epilogue. R8 skeleton: 128x128 tile, XOR swizzle,
// 1 barrier/chunk, 2 CTAs/SM; now 24KB stages -> 4-stage pipeline.
// ---------------------------------------------------------------------------

#define DD 512
#define NQ  8192
#define NKV 32768
#define EPS 1e-5f
#define WSCALE 4096.0f
#define WINV   (1.0f / 4096.0f)

// fp32 scratch planes
#define F_Q   0
#define F_AO  (F_Q  + (size_t)NQ * DD)
#define F_O1  (F_AO + (size_t)NQ * DD)
#define F_FF  (F_O1 + (size_t)NQ * DD)
#define F_WP  (F_FF + (size_t)NQ * DD)          // w_part [NKV][16]
#define F_SW  (F_WP + (size_t)NKV * 16)         // sum-of-w [NQ]
#define F_TOT (F_SW + (size_t)NQ)
__device__ float g_scratch[F_TOT];

// fp16 activation planes (single, no lo)
#define B_QH  0
#define B_KH  (B_QH  + (size_t)NQ  * DD)
#define B_VH  (B_KH  + (size_t)NKV * DD)        // downsampled value (NQ rows)
#define B_O1H (B_VH  + (size_t)NQ  * DD)
#define B_HH  (B_O1H + (size_t)NQ  * DD)
#define B_TOT (B_HH  + (size_t)NQ  * DD)
__device__ __half g_act[B_TOT];

// 5 weights x (hi,lo) x 512x512 fp16, stored [N][K] (transposed), x4096
__device__ __half g_wsplit[5u * 2u * 512u * 512u];

// ---------------------------------------------------------------------------
// PTX helpers (base sm_100-legal)
// ---------------------------------------------------------------------------
__device__ __forceinline__ uint32_t smem_u32(const void* p) {
    uint32_t a;
    asm("{ .reg .u64 t; cvta.to.shared.u64 t, %1; cvt.u32.u64 %0, t; }"
        : "=r"(a) : "l"(p));
    return a;
}
__device__ __forceinline__ void ldsm_x4(uint32_t* r, uint32_t addr) {
    asm volatile("ldmatrix.sync.aligned.m8n8.x4.shared.b16 {%0,%1,%2,%3}, [%4];"
                 : "=r"(r[0]), "=r"(r[1]), "=r"(r[2]), "=r"(r[3]) : "r"(addr));
}
__device__ __forceinline__ void mma16816(float* c, const uint32_t* a, const uint32_t* b) {
    asm volatile(
        "mma.sync.aligned.m16n8k16.row.col.f32.f16.f16.f32 "
        "{%0,%1,%2,%3}, {%4,%5,%6,%7}, {%8,%9}, {%0,%1,%2,%3};"
        : "+f"(c[0]), "+f"(c[1]), "+f"(c[2]), "+f"(c[3])
        : "r"(a[0]), "r"(a[1]), "r"(a[2]), "r"(a[3]), "r"(b[0]), "r"(b[1]));
}
__device__ __forceinline__ void cp16(uint32_t saddr, const void* g) {
    asm volatile("cp.async.cg.shared.global [%0], [%1], 16;"
                 :: "r"(saddr), "l"(g) : "memory");
}
__device__ __forceinline__ void cp_commit() {
    asm volatile("cp.async.commit_group;" ::: "memory");
}

// swizzled byte offset of 16B chunk (row, chunk) in a 128x64B plane
__device__ __forceinline__ uint32_t swz_off(uint32_t row, uint32_t chunk) {
    return row * 64u + ((chunk ^ ((row >> 1) & 3u)) << 4);
}

// ---------------------------------------------------------------------------
// Batched weight prep: W[k][n] fp32 -> Th[n][k], Tl[n][k] fp16, scaled x4096
// ---------------------------------------------------------------------------
__global__ void prep_weight5(
    const float* w0, const float* w1, const float* w2, const float* w3, const float* w4,
    __half* base)
{
    const float* Ws[5] = {w0, w1, w2, w3, w4};
    const size_t WSZ = 512u * 512u;
    const float* W = Ws[blockIdx.z];
    __half* Th = base + (size_t)blockIdx.z * 2u * WSZ;
    __half* Tl = Th + WSZ;

    __shared__ float t[32][33];
    const int bx = blockIdx.x * 32, by = blockIdx.y * 32;
    const int tx = threadIdx.x, ty = threadIdx.y; // 32 x 8
#pragma unroll
    for (int i = 0; i < 32; i += 8)
        t[ty + i][tx] = W[(size_t)(by + ty + i) * DD + bx + tx];
    __syncthreads();
#pragma unroll
    for (int i = 0; i < 32; i += 8) {
        float xs = t[tx][ty + i] * WSCALE;
        __half h = __float2half_rn(xs);
        __half l = __float2half_rn(xs - __half2float(h));
        size_t o = (size_t)(bx + ty + i) * DD + by + tx;
        Th[o] = h;
        Tl[o] = l;
    }
}

// ---------------------------------------------------------------------------
// fp32 -> fp16 convert (vectorized, single plane)
// ---------------------------------------------------------------------------
__global__ void __launch_bounds__(256) f32_to_h(
    const float4* __restrict__ src, uint2* __restrict__ dh)
{
    const int i = blockIdx.x * 256 + threadIdx.x;
    float4 x = src[i];
    __half2 h01, h23;
    h01.x = __float2half_rn(x.x); h01.y = __float2half_rn(x.y);
    h23.x = __float2half_rn(x.z); h23.y = __float2half_rn(x.w);
    uint2 hv;
    hv.x = *(uint32_t*)&h01; hv.y = *(uint32_t*)&h23;
    dh[i] = hv;
}

// ---------------------------------------------------------------------------
// HMMA GEMM: act(A[M,512] @ W[512,512] + bias), A fp16 single, W fp16 hi/lo
// scaled x4096 (epilogue multiplies acc by 1/4096).
// BM=128, BN=128, BK=32, 256 thr (8 warps 2m x 4n; warp tile 64x32).
// 4-stage cp.async pipeline (24KB stages: Ah|Bh|Bl), XOR swizzle,
// 1 barrier/chunk, launch_bounds(256,2) -> 2 CTAs/SM.
// DOTQ: k rows dotted with q rows instead of stored (w partials out).
// OUT_H: write single fp16 plane.
// ---------------------------------------------------------------------------
#define BKC 32
#define NCH (DD / BKC)          // 16
#define PLANE 8192              // 128 rows x 64B, swizzled
#define SG_AH 0
#define SG_BH (1 * PLANE)
#define SG_BL (2 * PLANE)
#define SG_SZ (3 * PLANE)       // 24576
#define STAGES 4
#define GEMM_SMEM (STAGES * SG_SZ) // 98304

template <bool RELU, bool OUT_H, bool DOTQ, bool HASBIAS>
__global__ void __launch_bounds__(256, 2) gemm_hl(
    const __half* __restrict__ Ah,
    const __half* __restrict__ Bh, const __half* __restrict__ Bl,
    const float* __restrict__ bias, float* __restrict__ C,
    __half* __restrict__ Ch,
    const float* __restrict__ qdot, float* __restrict__ wpart)
{
    extern __shared__ char sm[];
    const uint32_t sb = smem_u32(sm);

    const int tid = threadIdx.x;
    const int lane = tid & 31, wid = tid >> 5;
    const int wm = (wid & 1) * 64;
    const int wn = (wid >> 1) * 32;
    const int bm = blockIdx.y * 128;
    const int bn = blockIdx.x * 128;

    float acc[4][4][4];
#pragma unroll
    for (int i = 0; i < 4; i++)
#pragma unroll
        for (int j = 0; j < 4; j++)
#pragma unroll
            for (int t = 0; t < 4; t++) acc[i][j][t] = 0.f;

    const uint32_t row0 = (uint32_t)(tid >> 2), seg0 = (uint32_t)(tid & 3);
    const uint32_t row1 = row0 + 64;

    auto load_stage = [&](int c, int buf) {
        const uint32_t st = sb + buf * SG_SZ;
        const int kc = c * BKC;
        {
            uint32_t so = swz_off(row0, seg0);
            size_t ga = (size_t)(bm + row0) * DD + kc + seg0 * 8;
            size_t gb = (size_t)(bn + row0) * DD + kc + seg0 * 8;
            cp16(st + SG_AH + so, Ah + ga);
            cp16(st + SG_BH + so, Bh + gb);
            cp16(st + SG_BL + so, Bl + gb);
        }
        {
            uint32_t so = swz_off(row1, seg0);
            size_t ga = (size_t)(bm + row1) * DD + kc + seg0 * 8;
            size_t gb = (size_t)(bn + row1) * DD + kc + seg0 * 8;
            cp16(st + SG_AH + so, Ah + ga);
            cp16(st + SG_BH + so, Bh + gb);
            cp16(st + SG_BL + so, Bl + gb);
        }
        cp_commit();
    };

    const uint32_t a_r = (uint32_t)(wm + (lane & 15));
    const uint32_t a_ch = (uint32_t)(lane >> 4);        // chunk half (0/1)
    const uint32_t b_r = (uint32_t)(wn + ((lane >> 4) << 3) + (lane & 7));
    const uint32_t b_ch = (uint32_t)((lane >> 3) & 1);

    auto compute = [&](int buf) {
        const uint32_t st = sb + buf * SG_SZ;
#pragma unroll
        for (int ks = 0; ks < 2; ks++) {
            uint32_t ah[4][4], bh[2][4], bl[2][4];
            const uint32_t kch = (uint32_t)(ks * 2);
#pragma unroll
            for (int i = 0; i < 4; i++) {
                uint32_t off = swz_off(a_r + i * 16, kch + a_ch);
                ldsm_x4(ah[i], st + SG_AH + off);
            }
#pragma unroll
            for (int jp = 0; jp < 2; jp++) {
                uint32_t off = swz_off(b_r + jp * 16, kch + b_ch);
                ldsm_x4(bh[jp], st + SG_BH + off);
                ldsm_x4(bl[jp], st + SG_BL + off);
            }
#pragma unroll
            for (int i = 0; i < 4; i++)
#pragma unroll
                for (int j = 0; j < 4; j++)
                    mma16816(acc[i][j], ah[i], &bh[j >> 1][(j & 1) * 2]);
#pragma unroll
            for (int i = 0; i < 4; i++)
#pragma unroll
                for (int j = 0; j < 4; j++)
                    mma16816(acc[i][j], ah[i], &bl[j >> 1][(j & 1) * 2]);
        }
    };

    // 4-stage pipeline, one barrier per chunk.
    load_stage(0, 0);
    load_stage(1, 1);
    load_stage(2, 2);

#pragma unroll 1
    for (int c = 0; c < NCH; c++) {
        if (c < NCH - 2)
            asm volatile("cp.async.wait_group 2;" ::: "memory");
        else if (c == NCH - 2)
            asm volatile("cp.async.wait_group 1;" ::: "memory");
        else
            asm volatile("cp.async.wait_group 0;" ::: "memory");
        __syncthreads();
        if (c + 3 < NCH) load_stage(c + 3, (c + 3) & 3);
        compute(c & 3);
    }

    // ---------------- epilogue (acc is scaled by 4096; undo first) ---------
    const int crow = lane >> 2, ccol = (lane & 3) * 2;

    if (DOTQ) {
        float dotr[4][2];
#pragma unroll
        for (int i = 0; i < 4; i++) { dotr[i][0] = 0.f; dotr[i][1] = 0.f; }
#pragma unroll
        for (int i = 0; i < 4; i++) {
            const int r0 = bm + wm + i * 16 + crow;
            const float* q0p = qdot + (size_t)(r0 >> 2) * DD;
            const float* q1p = qdot + (size_t)((r0 + 8) >> 2) * DD;
#pragma unroll
            for (int j = 0; j < 4; j++) {
                const int col = bn + wn + j * 8 + ccol;
                float bx = 0.f, by = 0.f;
                if (HASBIAS) {
                    float2 bv = *(const float2*)(bias + col);
                    bx = bv.x; by = bv.y;
                }
                float k00 = fmaxf(acc[i][j][0] * WINV + bx, 0.f);
                float k01 = fmaxf(acc[i][j][1] * WINV + by, 0.f);
                float k10 = fmaxf(acc[i][j][2] * WINV + bx, 0.f);
                float k11 = fmaxf(acc[i][j][3] * WINV + by, 0.f);
                float2 q0 = *(const float2*)(q0p + col);
                float2 q1 = *(const float2*)(q1p + col);
                dotr[i][0] += k00 * q0.x + k01 * q0.y;
                dotr[i][1] += k10 * q1.x + k11 * q1.y;
            }
        }
#pragma unroll
        for (int i = 0; i < 4; i++)
#pragma unroll
            for (int p = 0; p < 2; p++) {
                float v = dotr[i][p];
                v += __shfl_xor_sync(0xffffffffu, v, 1);
                v += __shfl_xor_sync(0xffffffffu, v, 2);
                if ((lane & 3) == 0) {
                    const int row = bm + wm + i * 16 + crow + p * 8;
                    wpart[(size_t)row * 16 + blockIdx.x * 4 + (wid >> 1)] = v;
                }
            }
        return;
    }

#pragma unroll
    for (int i = 0; i < 4; i++) {
        const int r0 = bm + wm + i * 16 + crow;
#pragma unroll
        for (int j = 0; j < 4; j++) {
            const int col = bn + wn + j * 8 + ccol;
            float bx = 0.f, by = 0.f;
            if (HASBIAS) {
                float2 bv = *(const float2*)(bias + col);
                bx = bv.x; by = bv.y;
            }
            float2 o0, o1;
            o0.x = acc[i][j][0] * WINV + bx; o0.y = acc[i][j][1] * WINV + by;
            o1.x = acc[i][j][2] * WINV + bx; o1.y = acc[i][j][3] * WINV + by;
            if (RELU) {
                o0.x = fmaxf(o0.x, 0.f); o0.y = fmaxf(o0.y, 0.f);
                o1.x = fmaxf(o1.x, 0.f); o1.y = fmaxf(o1.y, 0.f);
            }
            if (OUT_H) {
                __half2 h2;
                h2.x = __float2half_rn(o0.x); h2.y = __float2half_rn(o0.y);
                *(__half2*)(Ch + (size_t)r0 * DD + col) = h2;
                h2.x = __float2half_rn(o1.x); h2.y = __float2half_rn(o1.y);
                *(__half2*)(Ch + (size_t)(r0 + 8) * DD + col) = h2;
            } else {
                *(float2*)(C + (size_t)r0 * DD + col) = o0;
                *(float2*)(C + (size_t)(r0 + 8) * DD + col) = o1;
            }
        }
    }
}

// ---------------------------------------------------------------------------
// Downsample: vds[s,:] = sum_f w[4s+f] * value[4s+f,:]; sw[s] = sum_f w.
// Emits vds as fp16 single plane.
// ---------------------------------------------------------------------------
__global__ void __launch_bounds__(256) wds_kernel(
    const float* __restrict__ wpart, const float* __restrict__ value,
    __half* __restrict__ vh, float* __restrict__ sw)
{
    const int s = blockIdx.x;
    const int tid = threadIdx.x;
    __shared__ float wp[64];
    __shared__ float wf[4];
    if (tid < 64) wp[tid] = wpart[(size_t)s * 64 + tid];
    __syncthreads();
    if (tid < 4) {
        float a = 0.f;
#pragma unroll
        for (int p = 0; p < 16; p++) a += wp[tid * 16 + p];
        wf[tid] = a;
    }
    __syncthreads();
    const float w0 = wf[0], w1 = wf[1], w2 = wf[2], w3 = wf[3];
    if (tid == 0) sw[s] = w0 + w1 + w2 + w3;

    const float* vr = value + (size_t)s * 4 * DD;
    const size_t o = (size_t)s * DD;
#pragma unroll
    for (int u = 0; u < 2; u++) {
        const int d = tid + u * 256;
        float x = w0 * vr[d] + w1 * vr[DD + d] + w2 * vr[2 * DD + d] + w3 * vr[3 * DD + d];
        vh[o + d] = __float2half_rn(x);
    }
}

// ---------------------------------------------------------------------------
// warp reduction
// ---------------------------------------------------------------------------
__device__ __forceinline__ float warp_sum(float x) {
#pragma unroll
    for (int o = 16; o > 0; o >>= 1) x += __shfl_xor_sync(0xffffffffu, x, o);
    return x;
}

// ---------------------------------------------------------------------------
// LN1: r = q + ao + sw*b_v; out1 = LN(r) (fp32 + fp16 plane)
// ---------------------------------------------------------------------------
__global__ void __launch_bounds__(256) attn_ln_kernel(
    const float* __restrict__ q, const float* __restrict__ ao,
    const float* __restrict__ sw, const float* __restrict__ bv,
    const float* __restrict__ gamma, const float* __restrict__ beta,
    float* __restrict__ out, __half* __restrict__ outh)
{
    const int row = blockIdx.x;
    const int tid = threadIdx.x;
    const int lane = tid & 31, wid = tid >> 5;
    const size_t off = (size_t)row * DD;
    const float swv = sw[row];

    float r0 = q[off + tid]       + ao[off + tid]       + swv * bv[tid];
    float r1 = q[off + tid + 256] + ao[off + tid + 256] + swv * bv[tid + 256];

    float s = warp_sum(r0 + r1);
    float ss = warp_sum(r0 * r0 + r1 * r1);
    __shared__ float rs[8], rss[8];
    if (lane == 0) { rs[wid] = s; rss[wid] = ss; }
    __syncthreads();
    __shared__ float mv[2];
    if (tid == 0) {
        float S = 0.f, SS = 0.f;
#pragma unroll
        for (int i = 0; i < 8; i++) { S += rs[i]; SS += rss[i]; }
        float mean = S * (1.f / 512.f);
        float var = SS * (1.f / 512.f) - mean * mean;
        mv[0] = mean; mv[1] = rsqrtf(var + EPS);
    }
    __syncthreads();
    const float mean = mv[0], inv = mv[1];
    float y0 = (r0 - mean) * inv * gamma[tid]       + beta[tid];
    float y1 = (r1 - mean) * inv * gamma[tid + 256] + beta[tid + 256];
    out[off + tid] = y0;
    out[off + tid + 256] = y1;
    outh[off + tid]       = __float2half_rn(y0);
    outh[off + tid + 256] = __float2half_rn(y1);
}

// ---------------------------------------------------------------------------
// Fused residual + LayerNorm2 -> output
// ---------------------------------------------------------------------------
__global__ void __launch_bounds__(256) resid_ln_kernel(
    const float* __restrict__ a, const float* __restrict__ f,
    const float* __restrict__ gamma, const float* __restrict__ beta,
    float* __restrict__ out)
{
    const int row = blockIdx.x;
    const int tid = threadIdx.x;
    const int lane = tid & 31, wid = tid >> 5;
    const size_t off = (size_t)row * DD;

    float r0 = a[off + tid]       + f[off + tid];
    float r1 = a[off + tid + 256] + f[off + tid + 256];

    float s = warp_sum(r0 + r1);
    float ss = warp_sum(r0 * r0 + r1 * r1);
    __shared__ float rs[8], rss[8];
    if (lane == 0) { rs[wid] = s; rss[wid] = ss; }
    __syncthreads();
    __shared__ float mv[2];
    if (tid == 0) {
        float S = 0.f, SS = 0.f;
#pragma unroll
        for (int i = 0; i < 8; i++) { S += rs[i]; SS += rss[i]; }
        float mean = S * (1.f / 512.f);
        float var = SS * (1.f / 512.f) - mean * mean;
        mv[0] = mean; mv[1] = rsqrtf(var + EPS);
    }
    __syncthreads();
    const float mean = mv[0], inv = mv[1];
    out[off + tid]       = (r0 - mean) * inv * gamma[tid]       + beta[tid];
    out[off + tid + 256] = (r1 - mean) * inv * gamma[tid + 256] + beta[tid + 256];
}

// ---------------------------------------------------------------------------
// Launch
// ---------------------------------------------------------------------------
extern "C" void kernel_launch(void* const* d_in, const int* in_sizes, int n_in,
                              void* d_out, int out_size)
{
    const float* query  = (const float*)d_in[0];
    const float* key    = (const float*)d_in[1];
    const float* value  = (const float*)d_in[2];
    const float* w_q    = (const float*)d_in[3];
    const float* b_q    = (const float*)d_in[4];
    const float* w_k    = (const float*)d_in[5];
    const float* b_k    = (const float*)d_in[6];
    const float* w_v    = (const float*)d_in[7];
    const float* b_v    = (const float*)d_in[8];
    const float* ln1_g  = (const float*)d_in[9];
    const float* ln1_b  = (const float*)d_in[10];
    const float* ln2_g  = (const float*)d_in[11];
    const float* ln2_b  = (const float*)d_in[12];
    const float* ffn_w1 = (const float*)d_in[13];
    const float* ffn_b1 = (const float*)d_in[14];
    const float* ffn_w2 = (const float*)d_in[15];
    const float* ffn_b2 = (const float*)d_in[16];
    float* out = (float*)d_out;

    void* sp = nullptr;
    cudaGetSymbolAddress(&sp, g_scratch);
    float* s = (float*)sp;
    float* g_q    = s + F_Q;
    float* g_ao   = s + F_AO;
    float* g_out1 = s + F_O1;
    float* g_ffn  = s + F_FF;
    float* g_wp   = s + F_WP;
    float* g_sw   = s + F_SW;

    void* ap = nullptr;
    cudaGetSymbolAddress(&ap, g_act);
    __half* a = (__half*)ap;
    __half* qh  = a + B_QH;
    __half* kh  = a + B_KH;
    __half* vh  = a + B_VH;
    __half* o1h = a + B_O1H;
    __half* hh  = a + B_HH;

    void* wp = nullptr;
    cudaGetSymbolAddress(&wp, g_wsplit);
    __half* w = (__half*)wp;
    const size_t WSZ = 512u * 512u;
    __half* wqh = w + 0 * 2 * WSZ; __half* wql = wqh + WSZ;
    __half* wkh = w + 1 * 2 * WSZ; __half* wkl = wkh + WSZ;
    __half* wvh = w + 2 * 2 * WSZ; __half* wvl = wvh + WSZ;
    __half* f1h = w + 3 * 2 * WSZ; __half* f1l = f1h + WSZ;
    __half* f2h = w + 4 * 2 * WSZ; __half* f2l = f2h + WSZ;

    cudaFuncSetAttribute((const void*)gemm_hl<true,  false, false, true >, cudaFuncAttributeMaxDynamicSharedMemorySize, GEMM_SMEM);
    cudaFuncSetAttribute((const void*)gemm_hl<true,  false, true,  true >, cudaFuncAttributeMaxDynamicSharedMemorySize, GEMM_SMEM);
    cudaFuncSetAttribute((const void*)gemm_hl<false, false, false, false>, cudaFuncAttributeMaxDynamicSharedMemorySize, GEMM_SMEM);
    cudaFuncSetAttribute((const void*)gemm_hl<true,  true,  false, true >, cudaFuncAttributeMaxDynamicSharedMemorySize, GEMM_SMEM);
    cudaFuncSetAttribute((const void*)gemm_hl<false, false, false, true >, cudaFuncAttributeMaxDynamicSharedMemorySize, GEMM_SMEM);

    const dim3 blk(256);

    prep_weight5<<<dim3(16, 16, 5), dim3(32, 8)>>>(w_q, w_k, w_v, ffn_w1, ffn_w2, w);
    f32_to_h<<<NQ  * DD / 1024, blk>>>((const float4*)query, (uint2*)qh);
    f32_to_h<<<NKV * DD / 1024, blk>>>((const float4*)key,   (uint2*)kh);

    const dim3 grid_q(DD / 128, NQ / 128);   // 4 x 64
    const dim3 grid_kv(DD / 128, NKV / 128); // 4 x 256

    // Q projection
    gemm_hl<true, false, false, true><<<grid_q, blk, GEMM_SMEM>>>(
        qh, wqh, wql, b_q, g_q, nullptr, nullptr, nullptr);

    // K projection with fused q.k dot -> w partials
    gemm_hl<true, false, true, true><<<grid_kv, blk, GEMM_SMEM>>>(
        kh, wkh, wkl, b_k, nullptr, nullptr, g_q, g_wp);

    // downsample raw value by w
    wds_kernel<<<NQ, blk>>>(g_wp, value, vh, g_sw);

    // V projection on downsampled rows
    gemm_hl<false, false, false, false><<<grid_q, blk, GEMM_SMEM>>>(
        vh, wvh, wvl, nullptr, g_ao, nullptr, nullptr, nullptr);

    // LN1
    attn_ln_kernel<<<NQ, blk>>>(g_q, g_ao, g_sw, b_v, ln1_g, ln1_b, g_out1, o1h);

    // FFN
    gemm_hl<true, true, false, true><<<grid_q, blk, GEMM_SMEM>>>(
        o1h, f1h, f1l, ffn_b1, nullptr, hh, nullptr, nullptr);
    gemm_hl<false, false, false, true><<<grid_q, blk, GEMM_SMEM>>>(
        hh, f2h, f2l, ffn_b2, g_ffn, nullptr, nullptr, nullptr);

    resid_ln_kernel<<<NQ, blk>>>(g_out1, g_ffn, ln2_g, ln2_b, out);
}

// round 12
// speedup vs baseline: 1.8875x; 1.3926x over previous
#include <cuda_runtime.h>
#include <cuda_bf16.h>
#include <cuda_fp16.h>
#include <cstdint>

// ---------------------------------------------------------------------------
// AttentionSampling: B=4, SQ=2048, SK=8192, D=H=512, F=4, fp32.
// Round 12: single-pass fp16 GEMMs (A fp16, W fp16, fp32 accum; rel_err
// budget ~4.5e-4 of 1e-3). R8 skeleton: 128x128 tile, XOR swizzle,
// 1 barrier/chunk, 2 CTAs/SM; 16KB stages -> 4-stage pipeline (64KB).
// ---------------------------------------------------------------------------

#define DD 512
#define NQ  8192
#define NKV 32768
#define EPS 1e-5f

// fp32 scratch planes
#define F_Q   0
#define F_AO  (F_Q  + (size_t)NQ * DD)
#define F_O1  (F_AO + (size_t)NQ * DD)
#define F_FF  (F_O1 + (size_t)NQ * DD)
#define F_WP  (F_FF + (size_t)NQ * DD)          // w_part [NKV][16]
#define F_SW  (F_WP + (size_t)NKV * 16)         // sum-of-w [NQ]
#define F_TOT (F_SW + (size_t)NQ)
__device__ float g_scratch[F_TOT];

// fp16 activation planes
#define B_QH  0
#define B_KH  (B_QH  + (size_t)NQ  * DD)
#define B_VH  (B_KH  + (size_t)NKV * DD)        // downsampled value (NQ rows)
#define B_O1H (B_VH  + (size_t)NQ  * DD)
#define B_HH  (B_O1H + (size_t)NQ  * DD)
#define B_TOT (B_HH  + (size_t)NQ  * DD)
__device__ __half g_act[B_TOT];

// 5 weights x 512x512 fp16, stored [N][K] (transposed)
__device__ __half g_wsplit[5u * 512u * 512u];

// ---------------------------------------------------------------------------
// PTX helpers (base sm_100-legal)
// ---------------------------------------------------------------------------
__device__ __forceinline__ uint32_t smem_u32(const void* p) {
    uint32_t a;
    asm("{ .reg .u64 t; cvta.to.shared.u64 t, %1; cvt.u32.u64 %0, t; }"
        : "=r"(a) : "l"(p));
    return a;
}
__device__ __forceinline__ void ldsm_x4(uint32_t* r, uint32_t addr) {
    asm volatile("ldmatrix.sync.aligned.m8n8.x4.shared.b16 {%0,%1,%2,%3}, [%4];"
                 : "=r"(r[0]), "=r"(r[1]), "=r"(r[2]), "=r"(r[3]) : "r"(addr));
}
__device__ __forceinline__ void mma16816(float* c, const uint32_t* a, const uint32_t* b) {
    asm volatile(
        "mma.sync.aligned.m16n8k16.row.col.f32.f16.f16.f32 "
        "{%0,%1,%2,%3}, {%4,%5,%6,%7}, {%8,%9}, {%0,%1,%2,%3};"
        : "+f"(c[0]), "+f"(c[1]), "+f"(c[2]), "+f"(c[3])
        : "r"(a[0]), "r"(a[1]), "r"(a[2]), "r"(a[3]), "r"(b[0]), "r"(b[1]));
}
__device__ __forceinline__ void cp16(uint32_t saddr, const void* g) {
    asm volatile("cp.async.cg.shared.global [%0], [%1], 16;"
                 :: "r"(saddr), "l"(g) : "memory");
}
__device__ __forceinline__ void cp_commit() {
    asm volatile("cp.async.commit_group;" ::: "memory");
}

// swizzled byte offset of 16B chunk (row, chunk) in a 128x64B plane
__device__ __forceinline__ uint32_t swz_off(uint32_t row, uint32_t chunk) {
    return row * 64u + ((chunk ^ ((row >> 1) & 3u)) << 4);
}

// ---------------------------------------------------------------------------
// Batched weight prep: W[k][n] fp32 -> T[n][k] fp16 (5 weights)
// ---------------------------------------------------------------------------
__global__ void prep_weight5(
    const float* w0, const float* w1, const float* w2, const float* w3, const float* w4,
    __half* base)
{
    const float* Ws[5] = {w0, w1, w2, w3, w4};
    const size_t WSZ = 512u * 512u;
    const float* W = Ws[blockIdx.z];
    __half* Th = base + (size_t)blockIdx.z * WSZ;

    __shared__ float t[32][33];
    const int bx = blockIdx.x * 32, by = blockIdx.y * 32;
    const int tx = threadIdx.x, ty = threadIdx.y; // 32 x 8
#pragma unroll
    for (int i = 0; i < 32; i += 8)
        t[ty + i][tx] = W[(size_t)(by + ty + i) * DD + bx + tx];
    __syncthreads();
#pragma unroll
    for (int i = 0; i < 32; i += 8) {
        size_t o = (size_t)(bx + ty + i) * DD + by + tx;
        Th[o] = __float2half_rn(t[tx][ty + i]);
    }
}

// ---------------------------------------------------------------------------
// fp32 -> fp16 convert (vectorized)
// ---------------------------------------------------------------------------
__global__ void __launch_bounds__(256) f32_to_h(
    const float4* __restrict__ src, uint2* __restrict__ dh)
{
    const int i = blockIdx.x * 256 + threadIdx.x;
    float4 x = src[i];
    __half2 h01, h23;
    h01.x = __float2half_rn(x.x); h01.y = __float2half_rn(x.y);
    h23.x = __float2half_rn(x.z); h23.y = __float2half_rn(x.w);
    uint2 hv;
    hv.x = *(uint32_t*)&h01; hv.y = *(uint32_t*)&h23;
    dh[i] = hv;
}

// ---------------------------------------------------------------------------
// HMMA GEMM: act(A[M,512] @ W[512,512] + bias), fp16 x fp16 -> fp32.
// BM=128, BN=128, BK=32, 256 thr (8 warps 2m x 4n; warp tile 64x32).
// 4-stage cp.async pipeline (16KB stages: Ah|Bh), XOR swizzle,
// 1 barrier/chunk, launch_bounds(256,2) -> 2 CTAs/SM.
// DOTQ: k rows dotted with q rows instead of stored (w partials out).
// OUT_H: write fp16 plane.
// ---------------------------------------------------------------------------
#define BKC 32
#define NCH (DD / BKC)          // 16
#define PLANE 8192              // 128 rows x 64B, swizzled
#define SG_AH 0
#define SG_BH (1 * PLANE)
#define SG_SZ (2 * PLANE)       // 16384
#define STAGES 4
#define GEMM_SMEM (STAGES * SG_SZ) // 65536

template <bool RELU, bool OUT_H, bool DOTQ, bool HASBIAS>
__global__ void __launch_bounds__(256, 2) gemm_h(
    const __half* __restrict__ Ah, const __half* __restrict__ Bh,
    const float* __restrict__ bias, float* __restrict__ C,
    __half* __restrict__ Ch,
    const float* __restrict__ qdot, float* __restrict__ wpart)
{
    extern __shared__ char sm[];
    const uint32_t sb = smem_u32(sm);

    const int tid = threadIdx.x;
    const int lane = tid & 31, wid = tid >> 5;
    const int wm = (wid & 1) * 64;
    const int wn = (wid >> 1) * 32;
    const int bm = blockIdx.y * 128;
    const int bn = blockIdx.x * 128;

    float acc[4][4][4];
#pragma unroll
    for (int i = 0; i < 4; i++)
#pragma unroll
        for (int j = 0; j < 4; j++)
#pragma unroll
            for (int t = 0; t < 4; t++) acc[i][j][t] = 0.f;

    const uint32_t row0 = (uint32_t)(tid >> 2), seg0 = (uint32_t)(tid & 3);
    const uint32_t row1 = row0 + 64;

    auto load_stage = [&](int c, int buf) {
        const uint32_t st = sb + buf * SG_SZ;
        const int kc = c * BKC;
        {
            uint32_t so = swz_off(row0, seg0);
            cp16(st + SG_AH + so, Ah + (size_t)(bm + row0) * DD + kc + seg0 * 8);
            cp16(st + SG_BH + so, Bh + (size_t)(bn + row0) * DD + kc + seg0 * 8);
        }
        {
            uint32_t so = swz_off(row1, seg0);
            cp16(st + SG_AH + so, Ah + (size_t)(bm + row1) * DD + kc + seg0 * 8);
            cp16(st + SG_BH + so, Bh + (size_t)(bn + row1) * DD + kc + seg0 * 8);
        }
        cp_commit();
    };

    const uint32_t a_r = (uint32_t)(wm + (lane & 15));
    const uint32_t a_ch = (uint32_t)(lane >> 4);        // chunk half (0/1)
    const uint32_t b_r = (uint32_t)(wn + ((lane >> 4) << 3) + (lane & 7));
    const uint32_t b_ch = (uint32_t)((lane >> 3) & 1);

    auto compute = [&](int buf) {
        const uint32_t st = sb + buf * SG_SZ;
#pragma unroll
        for (int ks = 0; ks < 2; ks++) {
            uint32_t ah[4][4], bh[2][4];
            const uint32_t kch = (uint32_t)(ks * 2);
#pragma unroll
            for (int i = 0; i < 4; i++) {
                uint32_t off = swz_off(a_r + i * 16, kch + a_ch);
                ldsm_x4(ah[i], st + SG_AH + off);
            }
#pragma unroll
            for (int jp = 0; jp < 2; jp++) {
                uint32_t off = swz_off(b_r + jp * 16, kch + b_ch);
                ldsm_x4(bh[jp], st + SG_BH + off);
            }
#pragma unroll
            for (int i = 0; i < 4; i++)
#pragma unroll
                for (int j = 0; j < 4; j++)
                    mma16816(acc[i][j], ah[i], &bh[j >> 1][(j & 1) * 2]);
        }
    };

    // 4-stage pipeline, one barrier per chunk.
    load_stage(0, 0);
    load_stage(1, 1);
    load_stage(2, 2);

#pragma unroll 1
    for (int c = 0; c < NCH; c++) {
        if (c < NCH - 2)
            asm volatile("cp.async.wait_group 2;" ::: "memory");
        else if (c == NCH - 2)
            asm volatile("cp.async.wait_group 1;" ::: "memory");
        else
            asm volatile("cp.async.wait_group 0;" ::: "memory");
        __syncthreads();
        if (c + 3 < NCH) load_stage(c + 3, (c + 3) & 3);
        compute(c & 3);
    }

    // ---------------- epilogue ----------------
    const int crow = lane >> 2, ccol = (lane & 3) * 2;

    if (DOTQ) {
        float dotr[4][2];
#pragma unroll
        for (int i = 0; i < 4; i++) { dotr[i][0] = 0.f; dotr[i][1] = 0.f; }
#pragma unroll
        for (int i = 0; i < 4; i++) {
            const int r0 = bm + wm + i * 16 + crow;
            const float* q0p = qdot + (size_t)(r0 >> 2) * DD;
            const float* q1p = qdot + (size_t)((r0 + 8) >> 2) * DD;
#pragma unroll
            for (int j = 0; j < 4; j++) {
                const int col = bn + wn + j * 8 + ccol;
                float bx = 0.f, by = 0.f;
                if (HASBIAS) {
                    float2 bv = *(const float2*)(bias + col);
                    bx = bv.x; by = bv.y;
                }
                float k00 = fmaxf(acc[i][j][0] + bx, 0.f);
                float k01 = fmaxf(acc[i][j][1] + by, 0.f);
                float k10 = fmaxf(acc[i][j][2] + bx, 0.f);
                float k11 = fmaxf(acc[i][j][3] + by, 0.f);
                float2 q0 = *(const float2*)(q0p + col);
                float2 q1 = *(const float2*)(q1p + col);
                dotr[i][0] += k00 * q0.x + k01 * q0.y;
                dotr[i][1] += k10 * q1.x + k11 * q1.y;
            }
        }
#pragma unroll
        for (int i = 0; i < 4; i++)
#pragma unroll
            for (int p = 0; p < 2; p++) {
                float v = dotr[i][p];
                v += __shfl_xor_sync(0xffffffffu, v, 1);
                v += __shfl_xor_sync(0xffffffffu, v, 2);
                if ((lane & 3) == 0) {
                    const int row = bm + wm + i * 16 + crow + p * 8;
                    wpart[(size_t)row * 16 + blockIdx.x * 4 + (wid >> 1)] = v;
                }
            }
        return;
    }

#pragma unroll
    for (int i = 0; i < 4; i++) {
        const int r0 = bm + wm + i * 16 + crow;
#pragma unroll
        for (int j = 0; j < 4; j++) {
            const int col = bn + wn + j * 8 + ccol;
            float bx = 0.f, by = 0.f;
            if (HASBIAS) {
                float2 bv = *(const float2*)(bias + col);
                bx = bv.x; by = bv.y;
            }
            float2 o0, o1;
            o0.x = acc[i][j][0] + bx; o0.y = acc[i][j][1] + by;
            o1.x = acc[i][j][2] + bx; o1.y = acc[i][j][3] + by;
            if (RELU) {
                o0.x = fmaxf(o0.x, 0.f); o0.y = fmaxf(o0.y, 0.f);
                o1.x = fmaxf(o1.x, 0.f); o1.y = fmaxf(o1.y, 0.f);
            }
            if (OUT_H) {
                __half2 h2;
                h2.x = __float2half_rn(o0.x); h2.y = __float2half_rn(o0.y);
                *(__half2*)(Ch + (size_t)r0 * DD + col) = h2;
                h2.x = __float2half_rn(o1.x); h2.y = __float2half_rn(o1.y);
                *(__half2*)(Ch + (size_t)(r0 + 8) * DD + col) = h2;
            } else {
                *(float2*)(C + (size_t)r0 * DD + col) = o0;
                *(float2*)(C + (size_t)(r0 + 8) * DD + col) = o1;
            }
        }
    }
}

// ---------------------------------------------------------------------------
// Downsample: vds[s,:] = sum_f w[4s+f] * value[4s+f,:]; sw[s] = sum_f w.
// ---------------------------------------------------------------------------
__global__ void __launch_bounds__(256) wds_kernel(
    const float* __restrict__ wpart, const float* __restrict__ value,
    __half* __restrict__ vh, float* __restrict__ sw)
{
    const int s = blockIdx.x;
    const int tid = threadIdx.x;
    __shared__ float wp[64];
    __shared__ float wf[4];
    if (tid < 64) wp[tid] = wpart[(size_t)s * 64 + tid];
    __syncthreads();
    if (tid < 4) {
        float a = 0.f;
#pragma unroll
        for (int p = 0; p < 16; p++) a += wp[tid * 16 + p];
        wf[tid] = a;
    }
    __syncthreads();
    const float w0 = wf[0], w1 = wf[1], w2 = wf[2], w3 = wf[3];
    if (tid == 0) sw[s] = w0 + w1 + w2 + w3;

    const float* vr = value + (size_t)s * 4 * DD;
    const size_t o = (size_t)s * DD;
#pragma unroll
    for (int u = 0; u < 2; u++) {
        const int d = tid + u * 256;
        float x = w0 * vr[d] + w1 * vr[DD + d] + w2 * vr[2 * DD + d] + w3 * vr[3 * DD + d];
        vh[o + d] = __float2half_rn(x);
    }
}

// ---------------------------------------------------------------------------
// warp reduction
// ---------------------------------------------------------------------------
__device__ __forceinline__ float warp_sum(float x) {
#pragma unroll
    for (int o = 16; o > 0; o >>= 1) x += __shfl_xor_sync(0xffffffffu, x, o);
    return x;
}

// ---------------------------------------------------------------------------
// LN1: r = q + ao + sw*b_v; out1 = LN(r) (fp32 + fp16 plane)
// ---------------------------------------------------------------------------
__global__ void __launch_bounds__(256) attn_ln_kernel(
    const float* __restrict__ q, const float* __restrict__ ao,
    const float* __restrict__ sw, const float* __restrict__ bv,
    const float* __restrict__ gamma, const float* __restrict__ beta,
    float* __restrict__ out, __half* __restrict__ outh)
{
    const int row = blockIdx.x;
    const int tid = threadIdx.x;
    const int lane = tid & 31, wid = tid >> 5;
    const size_t off = (size_t)row * DD;
    const float swv = sw[row];

    float r0 = q[off + tid]       + ao[off + tid]       + swv * bv[tid];
    float r1 = q[off + tid + 256] + ao[off + tid + 256] + swv * bv[tid + 256];

    float s = warp_sum(r0 + r1);
    float ss = warp_sum(r0 * r0 + r1 * r1);
    __shared__ float rs[8], rss[8];
    if (lane == 0) { rs[wid] = s; rss[wid] = ss; }
    __syncthreads();
    __shared__ float mv[2];
    if (tid == 0) {
        float S = 0.f, SS = 0.f;
#pragma unroll
        for (int i = 0; i < 8; i++) { S += rs[i]; SS += rss[i]; }
        float mean = S * (1.f / 512.f);
        float var = SS * (1.f / 512.f) - mean * mean;
        mv[0] = mean; mv[1] = rsqrtf(var + EPS);
    }
    __syncthreads();
    const float mean = mv[0], inv = mv[1];
    float y0 = (r0 - mean) * inv * gamma[tid]       + beta[tid];
    float y1 = (r1 - mean) * inv * gamma[tid + 256] + beta[tid + 256];
    out[off + tid] = y0;
    out[off + tid + 256] = y1;
    outh[off + tid]       = __float2half_rn(y0);
    outh[off + tid + 256] = __float2half_rn(y1);
}

// ---------------------------------------------------------------------------
// Fused residual + LayerNorm2 -> output
// ---------------------------------------------------------------------------
__global__ void __launch_bounds__(256) resid_ln_kernel(
    const float* __restrict__ a, const float* __restrict__ f,
    const float* __restrict__ gamma, const float* __restrict__ beta,
    float* __restrict__ out)
{
    const int row = blockIdx.x;
    const int tid = threadIdx.x;
    const int lane = tid & 31, wid = tid >> 5;
    const size_t off = (size_t)row * DD;

    float r0 = a[off + tid]       + f[off + tid];
    float r1 = a[off + tid + 256] + f[off + tid + 256];

    float s = warp_sum(r0 + r1);
    float ss = warp_sum(r0 * r0 + r1 * r1);
    __shared__ float rs[8], rss[8];
    if (lane == 0) { rs[wid] = s; rss[wid] = ss; }
    __syncthreads();
    __shared__ float mv[2];
    if (tid == 0) {
        float S = 0.f, SS = 0.f;
#pragma unroll
        for (int i = 0; i < 8; i++) { S += rs[i]; SS += rss[i]; }
        float mean = S * (1.f / 512.f);
        float var = SS * (1.f / 512.f) - mean * mean;
        mv[0] = mean; mv[1] = rsqrtf(var + EPS);
    }
    __syncthreads();
    const float mean = mv[0], inv = mv[1];
    out[off + tid]       = (r0 - mean) * inv * gamma[tid]       + beta[tid];
    out[off + tid + 256] = (r1 - mean) * inv * gamma[tid + 256] + beta[tid + 256];
}

// ---------------------------------------------------------------------------
// Launch
// ---------------------------------------------------------------------------
extern "C" void kernel_launch(void* const* d_in, const int* in_sizes, int n_in,
                              void* d_out, int out_size)
{
    const float* query  = (const float*)d_in[0];
    const float* key    = (const float*)d_in[1];
    const float* value  = (const float*)d_in[2];
    const float* w_q    = (const float*)d_in[3];
    const float* b_q    = (const float*)d_in[4];
    const float* w_k    = (const float*)d_in[5];
    const float* b_k    = (const float*)d_in[6];
    const float* w_v    = (const float*)d_in[7];
    const float* b_v    = (const float*)d_in[8];
    const float* ln1_g  = (const float*)d_in[9];
    const float* ln1_b  = (const float*)d_in[10];
    const float* ln2_g  = (const float*)d_in[11];
    const float* ln2_b  = (const float*)d_in[12];
    const float* ffn_w1 = (const float*)d_in[13];
    const float* ffn_b1 = (const float*)d_in[14];
    const float* ffn_w2 = (const float*)d_in[15];
    const float* ffn_b2 = (const float*)d_in[16];
    float* out = (float*)d_out;

    void* sp = nullptr;
    cudaGetSymbolAddress(&sp, g_scratch);
    float* s = (float*)sp;
    float* g_q    = s + F_Q;
    float* g_ao   = s + F_AO;
    float* g_out1 = s + F_O1;
    float* g_ffn  = s + F_FF;
    float* g_wp   = s + F_WP;
    float* g_sw   = s + F_SW;

    void* ap = nullptr;
    cudaGetSymbolAddress(&ap, g_act);
    __half* a = (__half*)ap;
    __half* qh  = a + B_QH;
    __half* kh  = a + B_KH;
    __half* vh  = a + B_VH;
    __half* o1h = a + B_O1H;
    __half* hh  = a + B_HH;

    void* wp = nullptr;
    cudaGetSymbolAddress(&wp, g_wsplit);
    __half* w = (__half*)wp;
    const size_t WSZ = 512u * 512u;
    __half* wqh = w + 0 * WSZ;
    __half* wkh = w + 1 * WSZ;
    __half* wvh = w + 2 * WSZ;
    __half* f1h = w + 3 * WSZ;
    __half* f2h = w + 4 * WSZ;

    cudaFuncSetAttribute((const void*)gemm_h<true,  false, false, true >, cudaFuncAttributeMaxDynamicSharedMemorySize, GEMM_SMEM);
    cudaFuncSetAttribute((const void*)gemm_h<true,  false, true,  true >, cudaFuncAttributeMaxDynamicSharedMemorySize, GEMM_SMEM);
    cudaFuncSetAttribute((const void*)gemm_h<false, false, false, false>, cudaFuncAttributeMaxDynamicSharedMemorySize, GEMM_SMEM);
    cudaFuncSetAttribute((const void*)gemm_h<true,  true,  false, true >, cudaFuncAttributeMaxDynamicSharedMemorySize, GEMM_SMEM);
    cudaFuncSetAttribute((const void*)gemm_h<false, false, false, true >, cudaFuncAttributeMaxDynamicSharedMemorySize, GEMM_SMEM);

    const dim3 blk(256);

    prep_weight5<<<dim3(16, 16, 5), dim3(32, 8)>>>(w_q, w_k, w_v, ffn_w1, ffn_w2, w);
    f32_to_h<<<NQ  * DD / 1024, blk>>>((const float4*)query, (uint2*)qh);
    f32_to_h<<<NKV * DD / 1024, blk>>>((const float4*)key,   (uint2*)kh);

    const dim3 grid_q(DD / 128, NQ / 128);   // 4 x 64
    const dim3 grid_kv(DD / 128, NKV / 128); // 4 x 256

    // Q projection
    gemm_h<true, false, false, true><<<grid_q, blk, GEMM_SMEM>>>(
        qh, wqh, b_q, g_q, nullptr, nullptr, nullptr);

    // K projection with fused q.k dot -> w partials
    gemm_h<true, false, true, true><<<grid_kv, blk, GEMM_SMEM>>>(
        kh, wkh, b_k, nullptr, nullptr, g_q, g_wp);

    // downsample raw value by w
    wds_kernel<<<NQ, blk>>>(g_wp, value, vh, g_sw);

    // V projection on downsampled rows
    gemm_h<false, false, false, false><<<grid_q, blk, GEMM_SMEM>>>(
        vh, wvh, nullptr, g_ao, nullptr, nullptr, nullptr);

    // LN1
    attn_ln_kernel<<<NQ, blk>>>(g_q, g_ao, g_sw, b_v, ln1_g, ln1_b, g_out1, o1h);

    // FFN
    gemm_h<true, true, false, true><<<grid_q, blk, GEMM_SMEM>>>(
        o1h, f1h, ffn_b1, nullptr, hh, nullptr, nullptr);
    gemm_h<false, false, false, true><<<grid_q, blk, GEMM_SMEM>>>(
        hh, f2h, ffn_b2, g_ffn, nullptr, nullptr, nullptr);

    resid_ln_kernel<<<NQ, blk>>>(g_out1, g_ffn, ln2_g, ln2_b, out);
}